// round 4
// baseline (speedup 1.0000x reference)
#include <cuda_runtime.h>
#include <cstdint>

#define Lq   4096
#define DIN  512
#define DOUTC 256
#define NH   4
#define HD   64
#define TI   16      // rows per CTA in attention kernel
#define CJ   32      // j-chunk

typedef unsigned long long ull;

// ---------------- scratch (device globals; no allocs allowed) ----------------
__device__ float g_Wh[Lq * DOUTC];    // 4 MB
__device__ float g_si[Lq * NH];
__device__ float g_sj[Lq * NH];
__device__ float g_att[Lq * DOUTC];   // 4 MB

__device__ __forceinline__ float lrelu(float x) { return fmaxf(x, 0.2f * x); }

__device__ __forceinline__ ull pack2(float x, float y) {
    ull r;
    asm("mov.b64 %0, {%1, %2};" : "=l"(r) : "f"(x), "f"(y));
    return r;
}
__device__ __forceinline__ void fma2(ull& d, ull a, ull b) {
    asm("fma.rn.f32x2 %0, %1, %2, %0;" : "+l"(d) : "l"(a), "l"(b));
}
__device__ __forceinline__ float2 unpack2(ull v) {
    float2 f;
    asm("mov.b64 {%0, %1}, %2;" : "=f"(f.x), "=f"(f.y) : "l"(v));
    return f;
}

// ---------------- generic 64x64-tile fp32 GEMM: C = A @ B^T (+bias) ----------
template <int K, int MODE>
__global__ void __launch_bounds__(256) gemm64_nt(const float* __restrict__ Aext,
                                                 const float* __restrict__ Bm,
                                                 float* __restrict__ Cext,
                                                 const float* __restrict__ bias) {
    __shared__ float As[16][68];
    __shared__ float Bs[16][68];
    const float* Am = (MODE == 0) ? Aext : g_att;
    float*       Cm = (MODE == 0) ? g_Wh : Cext;

    int tid = threadIdx.x;
    int m0 = blockIdx.y * 64, n0 = blockIdx.x * 64;
    int tx = tid & 15, ty = tid >> 4;

    float acc[4][4] = {};
    int r  = tid >> 2;
    int kk = (tid & 3) * 4;

    for (int k0 = 0; k0 < K; k0 += 16) {
        float4 av = *(const float4*)&Am[(size_t)(m0 + r) * K + k0 + kk];
        As[kk + 0][r] = av.x; As[kk + 1][r] = av.y;
        As[kk + 2][r] = av.z; As[kk + 3][r] = av.w;
        float4 bv = *(const float4*)&Bm[(size_t)(n0 + r) * K + k0 + kk];
        Bs[kk + 0][r] = bv.x; Bs[kk + 1][r] = bv.y;
        Bs[kk + 2][r] = bv.z; Bs[kk + 3][r] = bv.w;
        __syncthreads();
#pragma unroll
        for (int k = 0; k < 16; k++) {
            float a[4], b[4];
            *(float4*)a = *(const float4*)&As[k][ty * 4];
            *(float4*)b = *(const float4*)&Bs[k][tx * 4];
#pragma unroll
            for (int i = 0; i < 4; i++)
#pragma unroll
                for (int j = 0; j < 4; j++)
                    acc[i][j] += a[i] * b[j];
        }
        __syncthreads();
    }

    float4 bv = make_float4(0.f, 0.f, 0.f, 0.f);
    if (MODE == 1) bv = *(const float4*)&bias[n0 + tx * 4];
#pragma unroll
    for (int i = 0; i < 4; i++) {
        float4 o = make_float4(acc[i][0] + bv.x, acc[i][1] + bv.y,
                               acc[i][2] + bv.z, acc[i][3] + bv.w);
        *(float4*)&Cm[(size_t)(m0 + ty * 4 + i) * DOUTC + n0 + tx * 4] = o;
    }
}

// ---------------- s_i / s_j ----------------------------------------------------
__global__ void __launch_bounds__(256) s_kernel(const float* __restrict__ attn) {
    int gw = blockIdx.x * 8 + (threadIdx.x >> 5);
    int lane = threadIdx.x & 31;
    int l = gw >> 2, hh = gw & 3;
    const float* whp = &g_Wh[(size_t)l * DOUTC + hh * HD];
    float v0 = whp[lane], v1 = whp[lane + 32];
    const float* ap = &attn[hh * 2 * HD];
    float si = v0 * ap[lane]      + v1 * ap[lane + 32];
    float sj = v0 * ap[64 + lane] + v1 * ap[96 + lane];
#pragma unroll
    for (int o = 16; o; o >>= 1) {
        si += __shfl_xor_sync(0xffffffffu, si, o);
        sj += __shfl_xor_sync(0xffffffffu, sj, o);
    }
    if (lane == 0) { g_si[l * NH + hh] = si; g_sj[l * NH + hh] = sj; }
}

// ---------------- fused masked-softmax aggregation ---------------------------
// smem:
//   wh_s   : float [CJ][256]            32768 B  (also reused for final reduction)
//   w_s    : float [NH][CJ][18]          9216 B
//   mask_s : uint32[TI][128]             8192 B
//   si/m/rd: float4[TI] each              768 B
#define SM_WH   0
#define SM_W    32768
#define SM_MASK (32768 + 9216)
#define SM_SI   (SM_MASK + 8192)
#define SM_M    (SM_SI + TI * 16)
#define SM_RD   (SM_M + TI * 16)
#define SM_TOT  (SM_RD + TI * 16)

__global__ void __launch_bounds__(256, 2) gat_attn_kernel(const int* __restrict__ A) {
    extern __shared__ char smem[];
    float*    wh_s   = (float*)(smem + SM_WH);
    float*    w_s    = (float*)(smem + SM_W);
    uint32_t* mask_s = (uint32_t*)(smem + SM_MASK);
    float4*   si_s   = (float4*)(smem + SM_SI);
    float4*   m_s    = (float4*)(smem + SM_M);
    float4*   rd_s   = (float4*)(smem + SM_RD);
    const float* si_f = (const float*)si_s;
    const float* m_f  = (const float*)m_s;
    const float* rd_f = (const float*)rd_s;

    const float4* sjg = (const float4*)g_sj;

    int tid = threadIdx.x, lane = tid & 31, wid = tid >> 5;
    int i0 = blockIdx.x * TI;

    if (tid < TI) si_s[tid] = ((const float4*)g_si)[i0 + tid];

    // adjacency bitmask via ballot (A rows read exactly once, coalesced)
    for (int ii = 0; ii < TI; ii++) {
        const int* Arow = A + (size_t)(i0 + ii) * Lq;
#pragma unroll
        for (int t = 0; t < Lq / 256; t++) {
            int j = (t * 8 + wid) * 32 + lane;
            uint32_t b = __ballot_sync(0xffffffffu, Arow[j] > 0);
            if (lane == 0) mask_s[ii * 128 + t * 8 + wid] = b;
        }
    }
    __syncthreads();

    // phase 1: per-row m and 1/denom (lrelu monotone -> m = lrelu(si + max sj))
    for (int rr = wid; rr < TI; rr += 8) {
        float4 si = si_s[rr];
        float mx0 = -1e30f, mx1 = -1e30f, mx2 = -1e30f, mx3 = -1e30f;
        for (int t = 0; t < 128; t++) {
            uint32_t word = mask_s[rr * 128 + t];
            if (word & (1u << lane)) {
                float4 s = __ldg(&sjg[t * 32 + lane]);
                mx0 = fmaxf(mx0, s.x); mx1 = fmaxf(mx1, s.y);
                mx2 = fmaxf(mx2, s.z); mx3 = fmaxf(mx3, s.w);
            }
        }
#pragma unroll
        for (int o = 16; o; o >>= 1) {
            mx0 = fmaxf(mx0, __shfl_xor_sync(0xffffffffu, mx0, o));
            mx1 = fmaxf(mx1, __shfl_xor_sync(0xffffffffu, mx1, o));
            mx2 = fmaxf(mx2, __shfl_xor_sync(0xffffffffu, mx2, o));
            mx3 = fmaxf(mx3, __shfl_xor_sync(0xffffffffu, mx3, o));
        }
        bool has = mx0 > -1e29f;
        float m0 = has ? lrelu(si.x + mx0) : 0.f;
        float m1 = has ? lrelu(si.y + mx1) : 0.f;
        float m2 = has ? lrelu(si.z + mx2) : 0.f;
        float m3 = has ? lrelu(si.w + mx3) : 0.f;
        float s0 = 0.f, s1 = 0.f, s2 = 0.f, s3 = 0.f;
        for (int t = 0; t < 128; t++) {
            uint32_t word = mask_s[rr * 128 + t];
            if (word & (1u << lane)) {
                float4 s = __ldg(&sjg[t * 32 + lane]);
                s0 += __expf(lrelu(si.x + s.x) - m0);
                s1 += __expf(lrelu(si.y + s.y) - m1);
                s2 += __expf(lrelu(si.z + s.z) - m2);
                s3 += __expf(lrelu(si.w + s.w) - m3);
            }
        }
#pragma unroll
        for (int o = 16; o; o >>= 1) {
            s0 += __shfl_xor_sync(0xffffffffu, s0, o);
            s1 += __shfl_xor_sync(0xffffffffu, s1, o);
            s2 += __shfl_xor_sync(0xffffffffu, s2, o);
            s3 += __shfl_xor_sync(0xffffffffu, s3, o);
        }
        if (lane == 0) {
            m_s[rr]  = make_float4(m0, m1, m2, m3);
            rd_s[rr] = make_float4(has ? 1.f / s0 : 0.f, has ? 1.f / s1 : 0.f,
                                   has ? 1.f / s2 : 0.f, has ? 1.f / s3 : 0.f);
        }
    }
    __syncthreads();

    // ---------------- phase 2 ------------------------------------------------
    // warp wid: half = wid>>2 (j-half of chunk), head hC = wid&3 (64-col block)
    // lane: rg = lane>>2 (rows rg*2, rg*2+1), cg = lane&3 (16-col sub-block)
    int half = wid >> 2;
    int hC   = wid & 3;
    int rg   = lane >> 2;
    int cg   = lane & 3;

    // alpha-fill mapping: jj = tid&31, head hF = wid>>1, rows (wid&1)*8..+8
    int jjF = tid & 31;
    int hF  = wid >> 1;
    int rbF = (wid & 1) * 8;

    ull acc[2][8];
#pragma unroll
    for (int a = 0; a < 2; a++)
#pragma unroll
        for (int b = 0; b < 8; b++) acc[a][b] = 0ull;

    const float4* WhG = (const float4*)g_Wh;

    for (int j0 = 0; j0 < Lq; j0 += CJ) {
        // stage Wh chunk (CJ x 256 floats), coalesced
        {
            const float4* src = WhG + (size_t)j0 * 64;
            float4* dst = (float4*)wh_s;
#pragma unroll
            for (int k = 0; k < (CJ * 64) / 256; k++)
                dst[tid + k * 256] = src[tid + k * 256];
        }
        // fill alpha chunk
        {
            int jg = j0 + jjF;
            float sjv = g_sj[jg * NH + hF];
            int wo = jg >> 5;
            uint32_t sel = 1u << (jg & 31);
            float* wdst = w_s + (hF * CJ + jjF) * 18;
#pragma unroll
            for (int r = 0; r < 8; r++) {
                int row = rbF + r;
                float wv = 0.f;
                if (mask_s[row * 128 + wo] & sel) {
                    wv = __expf(lrelu(si_f[row * 4 + hF] + sjv) - m_f[row * 4 + hF])
                         * rd_f[row * 4 + hF];
                }
                wdst[row] = wv;
            }
        }
        __syncthreads();

        // compute: this warp's 16 j rows (half), 16 cols (hC*64 + cg*16), 2 rows (rg*2)
        const float* wp = w_s + (hC * CJ + half * 16) * 18 + rg * 2;
        const ulonglong2* whp =
            (const ulonglong2*)wh_s + (half * 16) * 64 + hC * 16 + cg * 4;
#pragma unroll 8
        for (int jj = 0; jj < 16; jj++) {
            float2 wf = *(const float2*)(wp + jj * 18);
            ull w0 = pack2(wf.x, wf.x);
            ull w1 = pack2(wf.y, wf.y);
            ulonglong2 b0 = whp[jj * 64 + 0];
            ulonglong2 b1 = whp[jj * 64 + 1];
            ulonglong2 b2 = whp[jj * 64 + 2];
            ulonglong2 b3 = whp[jj * 64 + 3];
            fma2(acc[0][0], w0, b0.x); fma2(acc[0][1], w0, b0.y);
            fma2(acc[0][2], w0, b1.x); fma2(acc[0][3], w0, b1.y);
            fma2(acc[0][4], w0, b2.x); fma2(acc[0][5], w0, b2.y);
            fma2(acc[0][6], w0, b3.x); fma2(acc[0][7], w0, b3.y);
            fma2(acc[1][0], w1, b0.x); fma2(acc[1][1], w1, b0.y);
            fma2(acc[1][2], w1, b1.x); fma2(acc[1][3], w1, b1.y);
            fma2(acc[1][4], w1, b2.x); fma2(acc[1][5], w1, b2.y);
            fma2(acc[1][6], w1, b3.x); fma2(acc[1][7], w1, b3.y);
        }
        __syncthreads();
    }

    // 2-way reduction across j-halves (warps 4-7 -> smem, warps 0-3 add + store)
    int colb = hC * 64 + cg * 16;
    if (half == 1) {
#pragma unroll
        for (int r = 0; r < 2; r++) {
            int row = rg * 2 + r;
            float* dst = wh_s + row * 256 + colb;
#pragma unroll
            for (int p = 0; p < 8; p++) {
                float2 v = unpack2(acc[r][p]);
                dst[p * 2] = v.x; dst[p * 2 + 1] = v.y;
            }
        }
    }
    __syncthreads();
    if (half == 0) {
#pragma unroll
        for (int r = 0; r < 2; r++) {
            int row = rg * 2 + r;
            const float* par = wh_s + row * 256 + colb;
            float o[16];
#pragma unroll
            for (int p = 0; p < 8; p++) {
                float2 v = unpack2(acc[r][p]);
                o[p * 2]     = v.x + par[p * 2];
                o[p * 2 + 1] = v.y + par[p * 2 + 1];
            }
            float* dst = g_att + (size_t)(i0 + row) * DOUTC + colb;
#pragma unroll
            for (int q = 0; q < 4; q++)
                *(float4*)(dst + q * 4) = *(const float4*)(o + q * 4);
        }
    }
}

// ---------------- launch ------------------------------------------------------
extern "C" void kernel_launch(void* const* d_in, const int* in_sizes, int n_in,
                              void* d_out, int out_size) {
    const float* h     = (const float*)d_in[0];
    const int*   A     = (const int*)d_in[1];
    const float* W     = (const float*)d_in[2];
    const float* attn  = (const float*)d_in[3];
    const float* out_w = (const float*)d_in[4];
    const float* out_b = (const float*)d_in[5];
    float*       out   = (float*)d_out;

    gemm64_nt<DIN, 0><<<dim3(DOUTC / 64, Lq / 64), 256>>>(h, W, nullptr, nullptr);
    s_kernel<<<(Lq * NH) / 8, 256>>>(attn);
    cudaFuncSetAttribute(gat_attn_kernel,
                         cudaFuncAttributeMaxDynamicSharedMemorySize, SM_TOT);
    gat_attn_kernel<<<Lq / TI, 256, SM_TOT>>>(A);
    gemm64_nt<DOUTC, 1><<<dim3(DOUTC / 64, Lq / 64), 256>>>(nullptr, out_w, out, out_b);
}

// round 5
// speedup vs baseline: 1.5355x; 1.5355x over previous
#include <cuda_runtime.h>
#include <cstdint>

#define Lq    4096
#define DIN   512
#define DOUTC 256
#define NH    4
#define HD    64
#define TI    32      // rows per CTA
#define TC    128     // cols per CTA (2 heads)
#define CJ    32      // j-chunk
#define NC    (Lq / CJ)

typedef unsigned long long ull;

// ---------------- scratch (device globals; no allocs allowed) ----------------
__device__ float g_Wh[Lq * DOUTC];    // 4 MB
__device__ float g_si[Lq * NH];
__device__ float g_sj[Lq * NH];
__device__ float g_att[Lq * DOUTC];   // 4 MB

__device__ __forceinline__ float lrelu(float x) { return fmaxf(x, 0.2f * x); }

__device__ __forceinline__ ull pack2(float x, float y) {
    ull r;
    asm("mov.b64 %0, {%1, %2};" : "=l"(r) : "f"(x), "f"(y));
    return r;
}
__device__ __forceinline__ void fma2(ull& d, ull a, ull b) {
    asm("fma.rn.f32x2 %0, %1, %2, %0;" : "+l"(d) : "l"(a), "l"(b));
}
__device__ __forceinline__ float2 unpack2(ull v) {
    float2 f;
    asm("mov.b64 {%0, %1}, %2;" : "=f"(f.x), "=f"(f.y) : "l"(v));
    return f;
}
__device__ __forceinline__ uint32_t s2u(const void* p) {
    uint32_t a;
    asm("{ .reg .u64 t; cvta.to.shared.u64 t, %1; cvt.u32.u64 %0, t; }"
        : "=r"(a) : "l"(p));
    return a;
}
__device__ __forceinline__ void cpa16(uint32_t dst, const float* src) {
    asm volatile("cp.async.cg.shared.global [%0], [%1], 16;"
                 :: "r"(dst), "l"(src));
}
#define CPA_COMMIT() asm volatile("cp.async.commit_group;")
#define CPA_WAIT0()  asm volatile("cp.async.wait_group 0;")

// ---------------- generic 64x64-tile fp32 GEMM: C = A @ B^T (+bias) ----------
template <int K, int MODE>
__global__ void __launch_bounds__(256) gemm64_nt(const float* __restrict__ Aext,
                                                 const float* __restrict__ Bm,
                                                 float* __restrict__ Cext,
                                                 const float* __restrict__ bias) {
    __shared__ float As[16][68];
    __shared__ float Bs[16][68];
    const float* Am = (MODE == 0) ? Aext : g_att;
    float*       Cm = (MODE == 0) ? g_Wh : Cext;

    int tid = threadIdx.x;
    int m0 = blockIdx.y * 64, n0 = blockIdx.x * 64;
    int tx = tid & 15, ty = tid >> 4;

    float acc[4][4] = {};
    int r  = tid >> 2;
    int kk = (tid & 3) * 4;

    for (int k0 = 0; k0 < K; k0 += 16) {
        float4 av = *(const float4*)&Am[(size_t)(m0 + r) * K + k0 + kk];
        As[kk + 0][r] = av.x; As[kk + 1][r] = av.y;
        As[kk + 2][r] = av.z; As[kk + 3][r] = av.w;
        float4 bv = *(const float4*)&Bm[(size_t)(n0 + r) * K + k0 + kk];
        Bs[kk + 0][r] = bv.x; Bs[kk + 1][r] = bv.y;
        Bs[kk + 2][r] = bv.z; Bs[kk + 3][r] = bv.w;
        __syncthreads();
#pragma unroll
        for (int k = 0; k < 16; k++) {
            float a[4], b[4];
            *(float4*)a = *(const float4*)&As[k][ty * 4];
            *(float4*)b = *(const float4*)&Bs[k][tx * 4];
#pragma unroll
            for (int i = 0; i < 4; i++)
#pragma unroll
                for (int j = 0; j < 4; j++)
                    acc[i][j] += a[i] * b[j];
        }
        __syncthreads();
    }

    float4 bv = make_float4(0.f, 0.f, 0.f, 0.f);
    if (MODE == 1) bv = *(const float4*)&bias[n0 + tx * 4];
#pragma unroll
    for (int i = 0; i < 4; i++) {
        float4 o = make_float4(acc[i][0] + bv.x, acc[i][1] + bv.y,
                               acc[i][2] + bv.z, acc[i][3] + bv.w);
        *(float4*)&Cm[(size_t)(m0 + ty * 4 + i) * DOUTC + n0 + tx * 4] = o;
    }
}

// ---------------- s_i / s_j ---------------------------------------------------
__global__ void __launch_bounds__(256) s_kernel(const float* __restrict__ attn) {
    int gw = blockIdx.x * 8 + (threadIdx.x >> 5);
    int lane = threadIdx.x & 31;
    int l = gw >> 2, hh = gw & 3;
    const float* whp = &g_Wh[(size_t)l * DOUTC + hh * HD];
    float v0 = whp[lane], v1 = whp[lane + 32];
    const float* ap = &attn[hh * 2 * HD];
    float si = v0 * ap[lane]      + v1 * ap[lane + 32];
    float sj = v0 * ap[64 + lane] + v1 * ap[96 + lane];
#pragma unroll
    for (int o = 16; o; o >>= 1) {
        si += __shfl_xor_sync(0xffffffffu, si, o);
        sj += __shfl_xor_sync(0xffffffffu, sj, o);
    }
    if (lane == 0) { g_si[l * NH + hh] = si; g_sj[l * NH + hh] = sj; }
}

// ---------------- fused masked-softmax aggregation ---------------------------
// smem layout:
//   wh_s   : 2 x [CJ][TC] floats        32768 B (double-buffered Wh chunk)
//   w_s    : 2 x [2][CJ][36] floats     18432 B (double-buffered alpha chunk)
//   mask_t : uint32[128][33]            16896 B (transposed, conflict-free)
//   si/m/rd: float[TI*2] each            2 heads per CTA, 768 B
#define W_STRIDE 36
#define SM_WH   0
#define SM_W    (2 * CJ * TC * 4)
#define SM_MASK (SM_W + 2 * 2 * CJ * W_STRIDE * 4)
#define SM_SI   (SM_MASK + 128 * 33 * 4)
#define SM_M    (SM_SI + TI * 2 * 4)
#define SM_RD   (SM_M + TI * 2 * 4)
#define SM_TOT  (SM_RD + TI * 2 * 4)

__global__ void __launch_bounds__(256) gat_attn_kernel(const int* __restrict__ A) {
    extern __shared__ char smem[];
    float*    wh_s   = (float*)(smem + SM_WH);     // [2][CJ][TC]
    float*    w_s    = (float*)(smem + SM_W);      // [2][2][CJ][36]
    uint32_t* mask_t = (uint32_t*)(smem + SM_MASK);
    float*    si_s   = (float*)(smem + SM_SI);     // [TI][2]
    float*    m_s    = (float*)(smem + SM_M);
    float*    rd_s   = (float*)(smem + SM_RD);

    int tid = threadIdx.x, lane = tid & 31, wid = tid >> 5;
    int iblk = blockIdx.x >> 1;
    int cblk = blockIdx.x & 1;
    int i0 = iblk * TI;
    int hbase = cblk * 2;
    int c0 = cblk * TC;

    if (tid < TI)
        *(float2*)&si_s[tid * 2] =
            *(const float2*)&g_si[(size_t)(i0 + tid) * NH + hbase];

    // adjacency bitmask via ballot, stored transposed [wordIdx][row]
    for (int ii = 0; ii < TI; ii++) {
        const int* Arow = A + (size_t)(i0 + ii) * Lq;
#pragma unroll
        for (int t = 0; t < Lq / 256; t++) {
            int j = (t * 8 + wid) * 32 + lane;
            uint32_t b = __ballot_sync(0xffffffffu, Arow[j] > 0);
            if (lane == 0) mask_t[(t * 8 + wid) * 33 + ii] = b;
        }
    }
    __syncthreads();

    // phase 1: per-row (2 heads) m and 1/denom
    for (int rr = wid; rr < TI; rr += 8) {
        float si0 = si_s[rr * 2], si1 = si_s[rr * 2 + 1];
        float mx0 = -1e30f, mx1 = -1e30f;
        for (int t = 0; t < 128; t++) {
            uint32_t word = mask_t[t * 33 + rr];
            if (word & (1u << lane)) {
                float2 s = __ldg((const float2*)&g_sj[(size_t)(t * 32 + lane) * NH + hbase]);
                mx0 = fmaxf(mx0, s.x); mx1 = fmaxf(mx1, s.y);
            }
        }
#pragma unroll
        for (int o = 16; o; o >>= 1) {
            mx0 = fmaxf(mx0, __shfl_xor_sync(0xffffffffu, mx0, o));
            mx1 = fmaxf(mx1, __shfl_xor_sync(0xffffffffu, mx1, o));
        }
        bool has = mx0 > -1e29f;
        float m0 = has ? lrelu(si0 + mx0) : 0.f;
        float m1 = has ? lrelu(si1 + mx1) : 0.f;
        float s0 = 0.f, s1 = 0.f;
        for (int t = 0; t < 128; t++) {
            uint32_t word = mask_t[t * 33 + rr];
            if (word & (1u << lane)) {
                float2 s = __ldg((const float2*)&g_sj[(size_t)(t * 32 + lane) * NH + hbase]);
                s0 += __expf(lrelu(si0 + s.x) - m0);
                s1 += __expf(lrelu(si1 + s.y) - m1);
            }
        }
#pragma unroll
        for (int o = 16; o; o >>= 1) {
            s0 += __shfl_xor_sync(0xffffffffu, s0, o);
            s1 += __shfl_xor_sync(0xffffffffu, s1, o);
        }
        if (lane == 0) {
            m_s[rr * 2] = m0;  m_s[rr * 2 + 1] = m1;
            rd_s[rr * 2] = has ? 1.f / s0 : 0.f;
            rd_s[rr * 2 + 1] = has ? 1.f / s1 : 0.f;
        }
    }
    __syncthreads();

    // ---------------- phase 2: pipelined chunks ------------------------------
    // staging: thread t loads 4 float4s of chunk -> wh_s[buf]
    uint32_t wh_u0 = s2u(wh_s);
    int st_jj = (tid * 4) >> 5;        // jj row of first float4 (4 consecutive f4s may span)
    // (use flat index mapping: idx = tid + k*256 -> jj = idx>>5, c4 = idx&31)

    // fill mapping: h = tid>>7, jjF = (tid>>2)&31, r0F = (tid&3)*8
    int hF  = tid >> 7;
    int jjF = (tid >> 2) & 31;
    int r0F = (tid & 3) * 8;

    // compute mapping: rg = tid>>6 (rows rg*8..+7), cq = tid&63 (cols cq*2,+1)
    int rg = tid >> 6;
    int cq = tid & 63;
    int hC = cq >> 5;                  // head within CTA (0/1)

    ull acc[4][2];
#pragma unroll
    for (int a = 0; a < 4; a++) { acc[a][0] = 0ull; acc[a][1] = 0ull; }

    // helper lambdas unrolled manually
    // ---- prologue: stage chunk 0, fill w chunk 0 ----
    {
#pragma unroll
        for (int k = 0; k < 4; k++) {
            int idx = tid + k * 256;
            int jj = idx >> 5, c4 = idx & 31;
            cpa16(wh_u0 + (uint32_t)idx * 16,
                  &g_Wh[(size_t)jj * DOUTC + c0 + c4 * 4]);
        }
        CPA_COMMIT();
        // fill w_s buf 0 for chunk 0
        int jg = jjF;
        float sjv = __ldg(&g_sj[(size_t)jg * NH + hbase + hF]);
        int wo = jg >> 5;
        uint32_t sel = 1u << (jg & 31);
        float* wdst = w_s + (hF * CJ + jjF) * W_STRIDE + r0F;
        float v[8];
#pragma unroll
        for (int r = 0; r < 8; r++) {
            int row = r0F + r;
            float wv = 0.f;
            if (mask_t[wo * 33 + row] & sel)
                wv = __expf(lrelu(si_s[row * 2 + hF] + sjv) - m_s[row * 2 + hF])
                     * rd_s[row * 2 + hF];
            v[r] = wv;
        }
        *(float4*)(wdst)     = *(float4*)(v);
        *(float4*)(wdst + 4) = *(float4*)(v + 4);
        CPA_WAIT0();
        __syncthreads();
    }

    const int wbufsz = 2 * CJ * W_STRIDE;   // floats per w buffer

    for (int c = 0; c < NC; c++) {
        int cur = c & 1;
        // prefetch chunk c+1
        if (c + 1 < NC) {
            int nb = (c + 1) & 1;
            int j0n = (c + 1) * CJ;
            uint32_t base = wh_u0 + (uint32_t)(nb * CJ * TC) * 4;
#pragma unroll
            for (int k = 0; k < 4; k++) {
                int idx = tid + k * 256;
                int jj = idx >> 5, c4 = idx & 31;
                cpa16(base + (uint32_t)idx * 16,
                      &g_Wh[(size_t)(j0n + jj) * DOUTC + c0 + c4 * 4]);
            }
            CPA_COMMIT();
        }

        // compute chunk c
        {
            const float* wbase  = w_s + cur * wbufsz + (hC * CJ) * W_STRIDE + rg * 8;
            const float* whbase = wh_s + cur * CJ * TC + cq * 2;
#pragma unroll 8
            for (int jj = 0; jj < CJ; jj++) {
                ulonglong2 wA = *(const ulonglong2*)(wbase + jj * W_STRIDE);
                ulonglong2 wB = *(const ulonglong2*)(wbase + jj * W_STRIDE + 4);
                float2 wh = *(const float2*)(whbase + jj * TC);
                ull b0 = pack2(wh.x, wh.x);
                ull b1 = pack2(wh.y, wh.y);
                fma2(acc[0][0], wA.x, b0); fma2(acc[0][1], wA.x, b1);
                fma2(acc[1][0], wA.y, b0); fma2(acc[1][1], wA.y, b1);
                fma2(acc[2][0], wB.x, b0); fma2(acc[2][1], wB.x, b1);
                fma2(acc[3][0], wB.y, b0); fma2(acc[3][1], wB.y, b1);
            }
        }

        // fill w_s for chunk c+1
        if (c + 1 < NC) {
            int nb = (c + 1) & 1;
            int jg = (c + 1) * CJ + jjF;
            float sjv = __ldg(&g_sj[(size_t)jg * NH + hbase + hF]);
            int wo = jg >> 5;
            uint32_t sel = 1u << (jg & 31);
            float* wdst = w_s + nb * wbufsz + (hF * CJ + jjF) * W_STRIDE + r0F;
            float v[8];
#pragma unroll
            for (int r = 0; r < 8; r++) {
                int row = r0F + r;
                float wv = 0.f;
                if (mask_t[wo * 33 + row] & sel)
                    wv = __expf(lrelu(si_s[row * 2 + hF] + sjv) - m_s[row * 2 + hF])
                         * rd_s[row * 2 + hF];
                v[r] = wv;
            }
            *(float4*)(wdst)     = *(float4*)(v);
            *(float4*)(wdst + 4) = *(float4*)(v + 4);
            CPA_WAIT0();
        }
        __syncthreads();
    }

    // writeback: rows rg*8+2p(+1), cols c0 + cq*2
#pragma unroll
    for (int p = 0; p < 4; p++) {
        float2 v0 = unpack2(acc[p][0]);   // col0: rows (2p, 2p+1)
        float2 v1 = unpack2(acc[p][1]);   // col1
        int row = i0 + rg * 8 + 2 * p;
        *(float2*)&g_att[(size_t)row * DOUTC + c0 + cq * 2] =
            make_float2(v0.x, v1.x);
        *(float2*)&g_att[(size_t)(row + 1) * DOUTC + c0 + cq * 2] =
            make_float2(v0.y, v1.y);
    }
}

// ---------------- launch ------------------------------------------------------
extern "C" void kernel_launch(void* const* d_in, const int* in_sizes, int n_in,
                              void* d_out, int out_size) {
    const float* h     = (const float*)d_in[0];
    const int*   A     = (const int*)d_in[1];
    const float* W     = (const float*)d_in[2];
    const float* attn  = (const float*)d_in[3];
    const float* out_w = (const float*)d_in[4];
    const float* out_b = (const float*)d_in[5];
    float*       out   = (float*)d_out;

    gemm64_nt<DIN, 0><<<dim3(DOUTC / 64, Lq / 64), 256>>>(h, W, nullptr, nullptr);
    s_kernel<<<(Lq * NH) / 8, 256>>>(attn);
    cudaFuncSetAttribute(gat_attn_kernel,
                         cudaFuncAttributeMaxDynamicSharedMemorySize, SM_TOT);
    gat_attn_kernel<<<(Lq / TI) * 2, 256, SM_TOT>>>(A);
    gemm64_nt<DOUTC, 1><<<dim3(DOUTC / 64, Lq / 64), 256>>>(nullptr, out_w, out, out_b);
}

// round 6
// speedup vs baseline: 2.3321x; 1.5188x over previous
#include <cuda_runtime.h>
#include <cstdint>

#define Lq    4096
#define DIN   512
#define DOUTC 256
#define NH    4
#define HD    64
#define TI    32      // rows per CTA
#define TC    128     // cols per CTA (2 heads)
#define CJ    32      // j-chunk
#define NC    (Lq / CJ)

typedef unsigned long long ull;

// ---------------- scratch (device globals; no allocs allowed) ----------------
__device__ float g_Wh[Lq * DOUTC];    // 4 MB
__device__ float g_si[Lq * NH];
__device__ float g_sj[Lq * NH];
__device__ float g_att[Lq * DOUTC];   // 4 MB

__device__ __forceinline__ float lrelu(float x) { return fmaxf(x, 0.2f * x); }

__device__ __forceinline__ ull pack2(float x, float y) {
    ull r;
    asm("mov.b64 %0, {%1, %2};" : "=l"(r) : "f"(x), "f"(y));
    return r;
}
__device__ __forceinline__ void fma2(ull& d, ull a, ull b) {
    asm("fma.rn.f32x2 %0, %1, %2, %0;" : "+l"(d) : "l"(a), "l"(b));
}
__device__ __forceinline__ float2 unpack2(ull v) {
    float2 f;
    asm("mov.b64 {%0, %1}, %2;" : "=f"(f.x), "=f"(f.y) : "l"(v));
    return f;
}
__device__ __forceinline__ uint32_t s2u(const void* p) {
    uint32_t a;
    asm("{ .reg .u64 t; cvta.to.shared.u64 t, %1; cvt.u32.u64 %0, t; }"
        : "=r"(a) : "l"(p));
    return a;
}
__device__ __forceinline__ void cpa16(uint32_t dst, const float* src) {
    asm volatile("cp.async.cg.shared.global [%0], [%1], 16;"
                 :: "r"(dst), "l"(src));
}
#define CPA_COMMIT() asm volatile("cp.async.commit_group;")
#define CPA_WAIT0()  asm volatile("cp.async.wait_group 0;")

// ---------------- generic 64x64-tile fp32 GEMM: C = A @ B^T (+bias) ----------
template <int K, int MODE>
__global__ void __launch_bounds__(256) gemm64_nt(const float* __restrict__ Aext,
                                                 const float* __restrict__ Bm,
                                                 float* __restrict__ Cext,
                                                 const float* __restrict__ bias) {
    __shared__ float As[16][68];
    __shared__ float Bs[16][68];
    const float* Am = (MODE == 0) ? Aext : g_att;
    float*       Cm = (MODE == 0) ? g_Wh : Cext;

    int tid = threadIdx.x;
    int m0 = blockIdx.y * 64, n0 = blockIdx.x * 64;
    int tx = tid & 15, ty = tid >> 4;

    float acc[4][4] = {};
    int r  = tid >> 2;
    int kk = (tid & 3) * 4;

    for (int k0 = 0; k0 < K; k0 += 16) {
        float4 av = *(const float4*)&Am[(size_t)(m0 + r) * K + k0 + kk];
        As[kk + 0][r] = av.x; As[kk + 1][r] = av.y;
        As[kk + 2][r] = av.z; As[kk + 3][r] = av.w;
        float4 bv = *(const float4*)&Bm[(size_t)(n0 + r) * K + k0 + kk];
        Bs[kk + 0][r] = bv.x; Bs[kk + 1][r] = bv.y;
        Bs[kk + 2][r] = bv.z; Bs[kk + 3][r] = bv.w;
        __syncthreads();
#pragma unroll
        for (int k = 0; k < 16; k++) {
            float a[4], b[4];
            *(float4*)a = *(const float4*)&As[k][ty * 4];
            *(float4*)b = *(const float4*)&Bs[k][tx * 4];
#pragma unroll
            for (int i = 0; i < 4; i++)
#pragma unroll
                for (int j = 0; j < 4; j++)
                    acc[i][j] += a[i] * b[j];
        }
        __syncthreads();
    }

    float4 bv = make_float4(0.f, 0.f, 0.f, 0.f);
    if (MODE == 1) bv = *(const float4*)&bias[n0 + tx * 4];
#pragma unroll
    for (int i = 0; i < 4; i++) {
        float4 o = make_float4(acc[i][0] + bv.x, acc[i][1] + bv.y,
                               acc[i][2] + bv.z, acc[i][3] + bv.w);
        *(float4*)&Cm[(size_t)(m0 + ty * 4 + i) * DOUTC + n0 + tx * 4] = o;
    }
}

// ---------------- s_i / s_j ---------------------------------------------------
__global__ void __launch_bounds__(256) s_kernel(const float* __restrict__ attn) {
    int gw = blockIdx.x * 8 + (threadIdx.x >> 5);
    int lane = threadIdx.x & 31;
    int l = gw >> 2, hh = gw & 3;
    const float* whp = &g_Wh[(size_t)l * DOUTC + hh * HD];
    float v0 = whp[lane], v1 = whp[lane + 32];
    const float* ap = &attn[hh * 2 * HD];
    float si = v0 * ap[lane]      + v1 * ap[lane + 32];
    float sj = v0 * ap[64 + lane] + v1 * ap[96 + lane];
#pragma unroll
    for (int o = 16; o; o >>= 1) {
        si += __shfl_xor_sync(0xffffffffu, si, o);
        sj += __shfl_xor_sync(0xffffffffu, sj, o);
    }
    if (lane == 0) { g_si[l * NH + hh] = si; g_sj[l * NH + hh] = sj; }
}

// ---------------- fused masked-softmax aggregation (no max pass) -------------
// alpha = exp(lrelu(si+sj)) * mask ; normalize by row-sum at the end.
// smem layout:
//   wh_s   : 2 x [CJ][TC] floats        32768 B (double-buffered Wh chunk)
//   w_s    : 2 x [2][CJ][36] floats     18432 B (double-buffered unnorm. alpha)
//   mask_t : uint32[128][36]            18432 B (transposed, uint4-loadable)
//   si_s   : float[TI][2]                 256 B
//   part_s : float[2][32][32]            8192 B (denominator partials)
//   dinv_s : float[32][2]                 256 B
#define W_STRIDE 36
#define MSTRIDE  36
#define SM_WH    0
#define SM_W     (2 * CJ * TC * 4)                    // 32768
#define SM_MASK  (SM_W + 2 * 2 * CJ * W_STRIDE * 4)   // 51200
#define SM_SI    (SM_MASK + 128 * MSTRIDE * 4)        // 69632
#define SM_PART  (SM_SI + TI * 2 * 4)                 // 69888
#define SM_DINV  (SM_PART + 2 * 32 * 32 * 4)          // 78080
#define SM_TOT   (SM_DINV + 32 * 2 * 4)               // 78336

__global__ void __launch_bounds__(256, 2) gat_attn_kernel(const int* __restrict__ A) {
    extern __shared__ char smem[];
    float*    wh_s   = (float*)(smem + SM_WH);     // [2][CJ][TC]
    float*    w_s    = (float*)(smem + SM_W);      // [2][2][CJ][36]
    uint32_t* mask_t = (uint32_t*)(smem + SM_MASK);
    float*    si_s   = (float*)(smem + SM_SI);     // [TI][2]
    float*    part_s = (float*)(smem + SM_PART);   // [2][32][32]
    float*    dinv_s = (float*)(smem + SM_DINV);   // [32][2]

    int tid = threadIdx.x, lane = tid & 31, wid = tid >> 5;
    int iblk = blockIdx.x >> 1;
    int cblk = blockIdx.x & 1;
    int i0 = iblk * TI;
    int hbase = cblk * 2;
    int c0 = cblk * TC;

    if (tid < TI)
        *(float2*)&si_s[tid * 2] =
            *(const float2*)&g_si[(size_t)(i0 + tid) * NH + hbase];

    // adjacency bitmask via ballot, stored transposed [wordIdx][row]
    for (int ii = 0; ii < TI; ii++) {
        const int* Arow = A + (size_t)(i0 + ii) * Lq;
#pragma unroll
        for (int t = 0; t < Lq / 256; t++) {
            int j = (t * 8 + wid) * 32 + lane;
            uint32_t b = __ballot_sync(0xffffffffu, Arow[j] > 0);
            if (lane == 0) mask_t[(t * 8 + wid) * MSTRIDE + ii] = b;
        }
    }
    __syncthreads();

    // ---------------- mappings ------------------------------------------------
    // fill: hF = tid>>7 (head), jjF = (tid>>2)&31 (j within chunk),
    //       r0F = (tid&3)*8 (8-row group)
    int hF  = tid >> 7;
    int jjF = (tid >> 2) & 31;
    int r0F = (tid & 3) * 8;
    // compute: rg = tid>>6 (8 rows), cq = tid&63 (2 cols), hC = cq>>5
    int rg = tid >> 6;
    int cq = tid & 63;
    int hC = cq >> 5;

    float si8[8];
#pragma unroll
    for (int r = 0; r < 8; r++) si8[r] = si_s[(r0F + r) * 2 + hF];
    float dsum[8] = {};

    ull acc[4][2];
#pragma unroll
    for (int a = 0; a < 4; a++) { acc[a][0] = 0ull; acc[a][1] = 0ull; }

    uint32_t wh_u0 = s2u(wh_s);
    const int wbufsz = 2 * CJ * W_STRIDE;

    // branchless fill of chunk c into buffer nb (+ denom accumulation)
#define DO_FILL(c, nb) do {                                                    \
        int jg = (c) * CJ + jjF;                                               \
        float sjv = __ldg(&g_sj[(size_t)jg * NH + hbase + hF]);                \
        uint32_t wsel = 1u << (jg & 31);                                       \
        const uint4* mwp = (const uint4*)&mask_t[(jg >> 5) * MSTRIDE + r0F];   \
        uint4 mw0 = mwp[0], mw1 = mwp[1];                                      \
        uint32_t mm[8] = {mw0.x, mw0.y, mw0.z, mw0.w,                          \
                          mw1.x, mw1.y, mw1.z, mw1.w};                         \
        float v[8];                                                            \
        _Pragma("unroll")                                                      \
        for (int r = 0; r < 8; r++) {                                          \
            float on = (mm[r] & wsel) ? 1.f : 0.f;                             \
            float x = si8[r] + sjv;                                            \
            float e = on * __expf(lrelu(x));                                   \
            dsum[r] += e;                                                      \
            v[r] = e;                                                          \
        }                                                                      \
        float* wdst = w_s + (nb) * wbufsz + (hF * CJ + jjF) * W_STRIDE + r0F;  \
        *(float4*)(wdst)     = *(float4*)(v);                                  \
        *(float4*)(wdst + 4) = *(float4*)(v + 4);                              \
    } while (0)

    // ---- prologue: stage + fill chunk 0 ----
    {
#pragma unroll
        for (int k = 0; k < 4; k++) {
            int idx = tid + k * 256;
            int jj = idx >> 5, c4 = idx & 31;
            cpa16(wh_u0 + (uint32_t)idx * 16,
                  &g_Wh[(size_t)jj * DOUTC + c0 + c4 * 4]);
        }
        CPA_COMMIT();
        DO_FILL(0, 0);
        CPA_WAIT0();
        __syncthreads();
    }

    for (int c = 0; c < NC; c++) {
        int cur = c & 1;
        if (c + 1 < NC) {
            int nb = (c + 1) & 1;
            int j0n = (c + 1) * CJ;
            uint32_t base = wh_u0 + (uint32_t)(nb * CJ * TC) * 4;
#pragma unroll
            for (int k = 0; k < 4; k++) {
                int idx = tid + k * 256;
                int jj = idx >> 5, c4 = idx & 31;
                cpa16(base + (uint32_t)idx * 16,
                      &g_Wh[(size_t)(j0n + jj) * DOUTC + c0 + c4 * 4]);
            }
            CPA_COMMIT();
        }

        // compute chunk c
        {
            const float* wbase  = w_s + cur * wbufsz + (hC * CJ) * W_STRIDE + rg * 8;
            const float* whbase = wh_s + cur * CJ * TC + cq * 2;
#pragma unroll 8
            for (int jj = 0; jj < CJ; jj++) {
                ulonglong2 wA = *(const ulonglong2*)(wbase + jj * W_STRIDE);
                ulonglong2 wB = *(const ulonglong2*)(wbase + jj * W_STRIDE + 4);
                float2 wh = *(const float2*)(whbase + jj * TC);
                ull b0 = pack2(wh.x, wh.x);
                ull b1 = pack2(wh.y, wh.y);
                fma2(acc[0][0], wA.x, b0); fma2(acc[0][1], wA.x, b1);
                fma2(acc[1][0], wA.y, b0); fma2(acc[1][1], wA.y, b1);
                fma2(acc[2][0], wB.x, b0); fma2(acc[2][1], wB.x, b1);
                fma2(acc[3][0], wB.y, b0); fma2(acc[3][1], wB.y, b1);
            }
        }

        if (c + 1 < NC) {
            DO_FILL(c + 1, (c + 1) & 1);
            CPA_WAIT0();
        }
        __syncthreads();
    }

    // ---- denominator reduction ----
#pragma unroll
    for (int r = 0; r < 8; r++)
        part_s[(hF * 32 + r0F + r) * 32 + jjF] = dsum[r];
    __syncthreads();
    if (tid < 64) {
        int h = tid >> 5, row = tid & 31;
        const float* pp = part_s + (h * 32 + row) * 32;
        float s = 0.f;
#pragma unroll
        for (int k = 0; k < 32; k++) s += pp[k];
        dinv_s[row * 2 + h] = (s > 0.f) ? 1.f / s : 0.f;
    }
    __syncthreads();

    // ---- normalized writeback ----
    float inv[8];
#pragma unroll
    for (int r = 0; r < 8; r++) inv[r] = dinv_s[(rg * 8 + r) * 2 + hC];
#pragma unroll
    for (int p = 0; p < 4; p++) {
        float2 v0 = unpack2(acc[p][0]);
        float2 v1 = unpack2(acc[p][1]);
        int row = i0 + rg * 8 + 2 * p;
        *(float2*)&g_att[(size_t)row * DOUTC + c0 + cq * 2] =
            make_float2(v0.x * inv[2 * p], v1.x * inv[2 * p]);
        *(float2*)&g_att[(size_t)(row + 1) * DOUTC + c0 + cq * 2] =
            make_float2(v0.y * inv[2 * p + 1], v1.y * inv[2 * p + 1]);
    }
}

// ---------------- launch ------------------------------------------------------
extern "C" void kernel_launch(void* const* d_in, const int* in_sizes, int n_in,
                              void* d_out, int out_size) {
    const float* h     = (const float*)d_in[0];
    const int*   A     = (const int*)d_in[1];
    const float* W     = (const float*)d_in[2];
    const float* attn  = (const float*)d_in[3];
    const float* out_w = (const float*)d_in[4];
    const float* out_b = (const float*)d_in[5];
    float*       out   = (float*)d_out;

    gemm64_nt<DIN, 0><<<dim3(DOUTC / 64, Lq / 64), 256>>>(h, W, nullptr, nullptr);
    s_kernel<<<(Lq * NH) / 8, 256>>>(attn);
    cudaFuncSetAttribute(gat_attn_kernel,
                         cudaFuncAttributeMaxDynamicSharedMemorySize, SM_TOT);
    gat_attn_kernel<<<(Lq / TI) * 2, 256, SM_TOT>>>(A);
    gemm64_nt<DOUTC, 1><<<dim3(DOUTC / 64, Lq / 64), 256>>>(nullptr, out_w, out, out_b);
}

// round 9
// speedup vs baseline: 5.0352x; 2.1591x over previous
#include <cuda_runtime.h>
#include <cstdint>

#define Lq    4096
#define DIN   512
#define DOUTC 256
#define NH    4
#define HD    64
#define CJ    32
#define NC    (Lq / CJ)

// ---------------- scratch (device globals; no allocs allowed) ----------------
__device__ float    g_Wh[Lq * DOUTC];     // [l][c] fp32
__device__ float    g_WhT[DOUTC * Lq];    // [c][l] tf32-rounded
__device__ float    g_att[Lq * DOUTC];
__device__ float    g_e1i[NH * Lq];       // exp(si)
__device__ float    g_e2i[NH * Lq];       // exp(0.2 si)
__device__ float    g_e1j[NH * Lq];       // exp(sj)
__device__ float    g_e2j[NH * Lq];       // exp(0.2 sj)
__device__ uint32_t g_maskT[(Lq / 32) * Lq];  // [word][row]

__device__ __forceinline__ uint32_t tf32r(float x) {
    uint32_t u;
    asm("cvt.rna.tf32.f32 %0, %1;" : "=r"(u) : "f"(x));
    return u;
}
__device__ __forceinline__ uint32_t s2u(const void* p) {
    uint32_t a;
    asm("{ .reg .u64 t; cvta.to.shared.u64 t, %1; cvt.u32.u64 %0, t; }"
        : "=r"(a) : "l"(p));
    return a;
}
__device__ __forceinline__ void cpa16(uint32_t dst, const void* src) {
    asm volatile("cp.async.cg.shared.global [%0], [%1], 16;"
                 :: "r"(dst), "l"(src));
}
#define CPA_COMMIT() asm volatile("cp.async.commit_group;")
#define CPA_WAIT0()  asm volatile("cp.async.wait_group 0;")

__device__ __forceinline__ void mma_tf32(float* c, uint32_t a0, uint32_t a1,
                                         uint32_t a2, uint32_t a3,
                                         uint32_t b0, uint32_t b1) {
    asm volatile(
        "mma.sync.aligned.m16n8k8.row.col.f32.tf32.tf32.f32 "
        "{%0,%1,%2,%3}, {%4,%5,%6,%7}, {%8,%9}, {%0,%1,%2,%3};"
        : "+f"(c[0]), "+f"(c[1]), "+f"(c[2]), "+f"(c[3])
        : "r"(a0), "r"(a1), "r"(a2), "r"(a3), "r"(b0), "r"(b1));
}

// ---------------- generic 64x64-tile fp32 GEMM: C = A @ B^T (+bias) ----------
template <int K, int MODE>
__global__ void __launch_bounds__(256) gemm64_nt(const float* __restrict__ Aext,
                                                 const float* __restrict__ Bm,
                                                 float* __restrict__ Cext,
                                                 const float* __restrict__ bias) {
    __shared__ float As[16][68];
    __shared__ float Bs[16][68];
    const float* Am = (MODE == 0) ? Aext : g_att;
    float*       Cm = (MODE == 0) ? g_Wh : Cext;

    int tid = threadIdx.x;
    int m0 = blockIdx.y * 64, n0 = blockIdx.x * 64;
    int tx = tid & 15, ty = tid >> 4;

    float acc[4][4] = {};
    int r  = tid >> 2;
    int kk = (tid & 3) * 4;

    for (int k0 = 0; k0 < K; k0 += 16) {
        float4 av = *(const float4*)&Am[(size_t)(m0 + r) * K + k0 + kk];
        As[kk + 0][r] = av.x; As[kk + 1][r] = av.y;
        As[kk + 2][r] = av.z; As[kk + 3][r] = av.w;
        float4 bv = *(const float4*)&Bm[(size_t)(n0 + r) * K + k0 + kk];
        Bs[kk + 0][r] = bv.x; Bs[kk + 1][r] = bv.y;
        Bs[kk + 2][r] = bv.z; Bs[kk + 3][r] = bv.w;
        __syncthreads();
#pragma unroll
        for (int k = 0; k < 16; k++) {
            float a[4], b[4];
            *(float4*)a = *(const float4*)&As[k][ty * 4];
            *(float4*)b = *(const float4*)&Bs[k][tx * 4];
#pragma unroll
            for (int i = 0; i < 4; i++)
#pragma unroll
                for (int j = 0; j < 4; j++)
                    acc[i][j] += a[i] * b[j];
        }
        __syncthreads();
    }

    float4 bv = make_float4(0.f, 0.f, 0.f, 0.f);
    if (MODE == 1) bv = *(const float4*)&bias[n0 + tx * 4];
#pragma unroll
    for (int i = 0; i < 4; i++) {
        float4 o = make_float4(acc[i][0] + bv.x, acc[i][1] + bv.y,
                               acc[i][2] + bv.z, acc[i][3] + bv.w);
        *(float4*)&Cm[(size_t)(m0 + ty * 4 + i) * DOUTC + n0 + tx * 4] = o;
    }
    if (MODE == 0) {
        // transposed tf32-rounded copy: B operand for the mma attention kernel
#pragma unroll
        for (int j = 0; j < 4; j++) {
            uint4 v;
            v.x = tf32r(acc[0][j]); v.y = tf32r(acc[1][j]);
            v.z = tf32r(acc[2][j]); v.w = tf32r(acc[3][j]);
            *(uint4*)&g_WhT[(size_t)(n0 + tx * 4 + j) * Lq + m0 + ty * 4] = v;
        }
    }
}

// ---------------- s kernel: E1/E2 factor tables ------------------------------
// exp(lrelu(si+sj)) == max(exp(si)exp(sj), exp(.2si)exp(.2sj))
__global__ void __launch_bounds__(256) s_kernel(const float* __restrict__ attn) {
    int gw = blockIdx.x * 8 + (threadIdx.x >> 5);
    int lane = threadIdx.x & 31;
    int l = gw >> 2, hh = gw & 3;
    const float* whp = &g_Wh[(size_t)l * DOUTC + hh * HD];
    float v0 = whp[lane], v1 = whp[lane + 32];
    const float* ap = &attn[hh * 2 * HD];
    float si = v0 * ap[lane]      + v1 * ap[lane + 32];
    float sj = v0 * ap[64 + lane] + v1 * ap[96 + lane];
#pragma unroll
    for (int o = 16; o; o >>= 1) {
        si += __shfl_xor_sync(0xffffffffu, si, o);
        sj += __shfl_xor_sync(0xffffffffu, sj, o);
    }
    if (lane == 0) {
        g_e1i[hh * Lq + l] = __expf(si);
        g_e2i[hh * Lq + l] = __expf(0.2f * si);
        g_e1j[hh * Lq + l] = __expf(sj);
        g_e2j[hh * Lq + l] = __expf(0.2f * sj);
    }
}

// ---------------- mask kernel: transposed bitmask [word][row] ----------------
__global__ void __launch_bounds__(256) mask_kernel(const int* __restrict__ A) {
    int lane = threadIdx.x & 31, wid = threadIdx.x >> 5;
    int row = blockIdx.x * 8 + wid;
    const int* Arow = A + (size_t)row * Lq;
    for (int w = 0; w < Lq / 32; w++) {
        uint32_t b = __ballot_sync(0xffffffffu, Arow[w * 32 + lane] > 0);
        if (lane == 0) g_maskT[(size_t)w * Lq + row] = b;
    }
}

// ---------------- mma.sync attention: 128 rows x 1 head per CTA --------------
// smem:
//   b_s    : 2 x [64][36] f32    18432 B (double-buffered WhT chunk, pad-36)
//   e1j/e2j: [4096] f32 each     32768 B
//   mask_s : [128][128] u32      65536 B
#define BPAD   36
#define BBUF   (64 * BPAD)
#define SM_B    0
#define SM_E1J  (2 * BBUF * 4)             // 18432
#define SM_E2J  (SM_E1J + Lq * 4)          // 34816
#define SM_MASK (SM_E2J + Lq * 4)          // 51200
#define SM_TOT  (SM_MASK + 128 * 128 * 4)  // 116736

__global__ void __launch_bounds__(256, 1) gat_attn_mma() {
    extern __shared__ char smem[];
    uint32_t smb = s2u(smem);
    float*    b_s    = (float*)(smem + SM_B);
    float*    e1j_s  = (float*)(smem + SM_E1J);
    float*    e2j_s  = (float*)(smem + SM_E2J);
    uint32_t* mask_s = (uint32_t*)(smem + SM_MASK);

    int tid = threadIdx.x, lane = tid & 31, wid = tid >> 5;
    int i0 = (blockIdx.x >> 2) * 128;
    int h  = blockIdx.x & 3;

    int q4 = lane & 3;        // k-in-group / col-pair selector
    int rg = lane >> 2;       // row within warp tile (0..7)
    int r1 = wid * 16 + rg;   // CTA-local rows
    int r2 = r1 + 8;

    // per-thread row factors
    float E1a = __ldg(&g_e1i[h * Lq + i0 + r1]);
    float E2a = __ldg(&g_e2i[h * Lq + i0 + r1]);
    float E1b = __ldg(&g_e1i[h * Lq + i0 + r2]);
    float E2b = __ldg(&g_e2i[h * Lq + i0 + r2]);

    // B prefetch of chunk c into buffer nb
#define PREF_B(c, nb) do {                                                     \
        _Pragma("unroll")                                                      \
        for (int q = 0; q < 2; q++) {                                          \
            int idx = tid + q * 256;                                           \
            int n = idx >> 3, k4 = idx & 7;                                    \
            cpa16(smb + SM_B + (nb) * BBUF * 4 + n * BPAD * 4 + k4 * 16,       \
                  &g_WhT[(size_t)(h * HD + n) * Lq + (c) * CJ + k4 * 4]);      \
        }                                                                      \
        CPA_COMMIT();                                                          \
    } while (0)

    // ---- prologue: stage mask + E tables + B chunk 0 ----
    PREF_B(0, 0);
#pragma unroll
    for (int q = 0; q < 16; q++) {         // FULL mask: 128 words x 128 rows
        int idx = tid + q * 256;           // 4096 x 16B = 64 KB
        int w = idx >> 5, r4 = idx & 31;
        cpa16(smb + SM_MASK + idx * 16, &g_maskT[(size_t)w * Lq + i0 + r4 * 4]);
    }
#pragma unroll
    for (int q = 0; q < 4; q++) {
        int idx = tid + q * 256;
        cpa16(smb + SM_E1J + idx * 16, &g_e1j[h * Lq + idx * 4]);
        cpa16(smb + SM_E2J + idx * 16, &g_e2j[h * Lq + idx * 4]);
    }
    CPA_COMMIT();
    CPA_WAIT0();
    __syncthreads();

    float c_acc[8][4];
#pragma unroll
    for (int t = 0; t < 8; t++)
#pragma unroll
        for (int p = 0; p < 4; p++) c_acc[t][p] = 0.f;
    float dsum1 = 0.f, dsum2 = 0.f;

    for (int c = 0; c < NC; c++) {
        int cur = c & 1;
        if (c + 1 < NC) PREF_B(c + 1, cur ^ 1);

        uint32_t mw1 = mask_s[c * 128 + r1] >> q4;
        uint32_t mw2 = mask_s[c * 128 + r2] >> q4;
        const float* bb = b_s + cur * BBUF + (lane >> 2) * BPAD;

#pragma unroll
        for (int ks = 0; ks < 4; ks++) {
            int j = c * CJ + ks * 8 + q4;
            float e1a = e1j_s[j],     e2a = e2j_s[j];
            float e1b = e1j_s[j + 4], e2b = e2j_s[j + 4];
            float m0 = fmaxf(E1a * e1a, E2a * e2a);
            float m1 = fmaxf(E1b * e1a, E2b * e2a);
            float m2 = fmaxf(E1a * e1b, E2a * e2b);
            float m3 = fmaxf(E1b * e1b, E2b * e2b);
            m0 = (mw1 & (1u << (ks * 8)))     ? m0 : 0.f;
            m1 = (mw2 & (1u << (ks * 8)))     ? m1 : 0.f;
            m2 = (mw1 & (1u << (ks * 8 + 4))) ? m2 : 0.f;
            m3 = (mw2 & (1u << (ks * 8 + 4))) ? m3 : 0.f;
            dsum1 += m0 + m2;
            dsum2 += m1 + m3;
            uint32_t a0 = tf32r(m0), a1 = tf32r(m1);
            uint32_t a2 = tf32r(m2), a3 = tf32r(m3);
#pragma unroll
            for (int t = 0; t < 8; t++) {
                uint32_t b0 = *(const uint32_t*)&bb[t * 8 * BPAD + ks * 8 + q4];
                uint32_t b1 = *(const uint32_t*)&bb[t * 8 * BPAD + ks * 8 + q4 + 4];
                mma_tf32(c_acc[t], a0, a1, a2, a3, b0, b1);
            }
        }

        if (c + 1 < NC) CPA_WAIT0();
        __syncthreads();
    }

    // denominator: reduce over the 4 lanes sharing a row
#pragma unroll
    for (int o = 1; o <= 2; o <<= 1) {
        dsum1 += __shfl_xor_sync(0xffffffffu, dsum1, o);
        dsum2 += __shfl_xor_sync(0xffffffffu, dsum2, o);
    }
    float inv1 = (dsum1 > 0.f) ? 1.f / dsum1 : 0.f;
    float inv2 = (dsum2 > 0.f) ? 1.f / dsum2 : 0.f;

    // writeback
    int col0 = h * HD + q4 * 2;
    float* d1 = g_att + (size_t)(i0 + r1) * DOUTC + col0;
    float* d2 = g_att + (size_t)(i0 + r2) * DOUTC + col0;
#pragma unroll
    for (int t = 0; t < 8; t++) {
        *(float2*)(d1 + t * 8) = make_float2(c_acc[t][0] * inv1, c_acc[t][1] * inv1);
        *(float2*)(d2 + t * 8) = make_float2(c_acc[t][2] * inv2, c_acc[t][3] * inv2);
    }
}

// ---------------- launch ------------------------------------------------------
extern "C" void kernel_launch(void* const* d_in, const int* in_sizes, int n_in,
                              void* d_out, int out_size) {
    const float* h     = (const float*)d_in[0];
    const int*   A     = (const int*)d_in[1];
    const float* W     = (const float*)d_in[2];
    const float* attn  = (const float*)d_in[3];
    const float* out_w = (const float*)d_in[4];
    const float* out_b = (const float*)d_in[5];
    float*       out   = (float*)d_out;

    gemm64_nt<DIN, 0><<<dim3(DOUTC / 64, Lq / 64), 256>>>(h, W, nullptr, nullptr);
    mask_kernel<<<Lq / 8, 256>>>(A);
    s_kernel<<<(Lq * NH) / 8, 256>>>(attn);
    cudaFuncSetAttribute(gat_attn_mma,
                         cudaFuncAttributeMaxDynamicSharedMemorySize, SM_TOT);
    gat_attn_mma<<<(Lq / 128) * NH, 256, SM_TOT>>>();
    gemm64_nt<DOUTC, 1><<<dim3(DOUTC / 64, Lq / 64), 256>>>(nullptr, out_w, out, out_b);
}

// round 10
// speedup vs baseline: 5.2949x; 1.0516x over previous
#include <cuda_runtime.h>
#include <cstdint>

#define Lq    4096
#define DIN   512
#define DOUTC 256
#define NH    4
#define HD    64
#define CJ    32
#define JC    64                 // chunks per CTA (half of K range)
#define JHALF 2048

// ---------------- scratch (device globals; no allocs allowed) ----------------
__device__ float    g_Wh[Lq * DOUTC];     // [l][c] fp32
__device__ float    g_WhT[DOUTC * Lq];    // [c][l] tf32-rounded
__device__ float    g_att[Lq * DOUTC];
__device__ float    g_patt[2 * Lq * DOUTC];   // j-split partial outputs
__device__ float    g_den[2 * NH * Lq];       // j-split partial denominators
__device__ float    g_e1i[NH * Lq];       // exp(si)
__device__ float    g_e2i[NH * Lq];       // exp(0.2 si)
__device__ float    g_e1j[NH * Lq];       // exp(sj)
__device__ float    g_e2j[NH * Lq];       // exp(0.2 sj)
__device__ uint32_t g_maskT[(Lq / 32) * Lq];  // [word][row]

__device__ __forceinline__ uint32_t tf32r(float x) {
    uint32_t u;
    asm("cvt.rna.tf32.f32 %0, %1;" : "=r"(u) : "f"(x));
    return u;
}
__device__ __forceinline__ uint32_t s2u(const void* p) {
    uint32_t a;
    asm("{ .reg .u64 t; cvta.to.shared.u64 t, %1; cvt.u32.u64 %0, t; }"
        : "=r"(a) : "l"(p));
    return a;
}
__device__ __forceinline__ void cpa16(uint32_t dst, const void* src) {
    asm volatile("cp.async.cg.shared.global [%0], [%1], 16;"
                 :: "r"(dst), "l"(src));
}
#define CPA_COMMIT() asm volatile("cp.async.commit_group;")
#define CPA_WAIT0()  asm volatile("cp.async.wait_group 0;")

__device__ __forceinline__ void mma_tf32(float* c, uint32_t a0, uint32_t a1,
                                         uint32_t a2, uint32_t a3,
                                         uint32_t b0, uint32_t b1) {
    asm volatile(
        "mma.sync.aligned.m16n8k8.row.col.f32.tf32.tf32.f32 "
        "{%0,%1,%2,%3}, {%4,%5,%6,%7}, {%8,%9}, {%0,%1,%2,%3};"
        : "+f"(c[0]), "+f"(c[1]), "+f"(c[2]), "+f"(c[3])
        : "r"(a0), "r"(a1), "r"(a2), "r"(a3), "r"(b0), "r"(b1));
}

// ---------------- generic 64x64-tile fp32 GEMM: C = A @ B^T (+bias) ----------
template <int K, int MODE>
__global__ void __launch_bounds__(256) gemm64_nt(const float* __restrict__ Aext,
                                                 const float* __restrict__ Bm,
                                                 float* __restrict__ Cext,
                                                 const float* __restrict__ bias) {
    __shared__ float As[16][68];
    __shared__ float Bs[16][68];
    const float* Am = (MODE == 0) ? Aext : g_att;
    float*       Cm = (MODE == 0) ? g_Wh : Cext;

    int tid = threadIdx.x;
    int m0 = blockIdx.y * 64, n0 = blockIdx.x * 64;
    int tx = tid & 15, ty = tid >> 4;

    float acc[4][4] = {};
    int r  = tid >> 2;
    int kk = (tid & 3) * 4;

    for (int k0 = 0; k0 < K; k0 += 16) {
        float4 av = *(const float4*)&Am[(size_t)(m0 + r) * K + k0 + kk];
        As[kk + 0][r] = av.x; As[kk + 1][r] = av.y;
        As[kk + 2][r] = av.z; As[kk + 3][r] = av.w;
        float4 bv = *(const float4*)&Bm[(size_t)(n0 + r) * K + k0 + kk];
        Bs[kk + 0][r] = bv.x; Bs[kk + 1][r] = bv.y;
        Bs[kk + 2][r] = bv.z; Bs[kk + 3][r] = bv.w;
        __syncthreads();
#pragma unroll
        for (int k = 0; k < 16; k++) {
            float a[4], b[4];
            *(float4*)a = *(const float4*)&As[k][ty * 4];
            *(float4*)b = *(const float4*)&Bs[k][tx * 4];
#pragma unroll
            for (int i = 0; i < 4; i++)
#pragma unroll
                for (int j = 0; j < 4; j++)
                    acc[i][j] += a[i] * b[j];
        }
        __syncthreads();
    }

    float4 bv = make_float4(0.f, 0.f, 0.f, 0.f);
    if (MODE == 1) bv = *(const float4*)&bias[n0 + tx * 4];
#pragma unroll
    for (int i = 0; i < 4; i++) {
        float4 o = make_float4(acc[i][0] + bv.x, acc[i][1] + bv.y,
                               acc[i][2] + bv.z, acc[i][3] + bv.w);
        *(float4*)&Cm[(size_t)(m0 + ty * 4 + i) * DOUTC + n0 + tx * 4] = o;
    }
    if (MODE == 0) {
        // transposed tf32-rounded copy: B operand for the mma attention kernel
#pragma unroll
        for (int j = 0; j < 4; j++) {
            uint4 v;
            v.x = tf32r(acc[0][j]); v.y = tf32r(acc[1][j]);
            v.z = tf32r(acc[2][j]); v.w = tf32r(acc[3][j]);
            *(uint4*)&g_WhT[(size_t)(n0 + tx * 4 + j) * Lq + m0 + ty * 4] = v;
        }
    }
}

// ---------------- s kernel: E1/E2 factor tables ------------------------------
// exp(lrelu(si+sj)) == max(exp(si)exp(sj), exp(.2si)exp(.2sj))
__global__ void __launch_bounds__(256) s_kernel(const float* __restrict__ attn) {
    int gw = blockIdx.x * 8 + (threadIdx.x >> 5);
    int lane = threadIdx.x & 31;
    int l = gw >> 2, hh = gw & 3;
    const float* whp = &g_Wh[(size_t)l * DOUTC + hh * HD];
    float v0 = whp[lane], v1 = whp[lane + 32];
    const float* ap = &attn[hh * 2 * HD];
    float si = v0 * ap[lane]      + v1 * ap[lane + 32];
    float sj = v0 * ap[64 + lane] + v1 * ap[96 + lane];
#pragma unroll
    for (int o = 16; o; o >>= 1) {
        si += __shfl_xor_sync(0xffffffffu, si, o);
        sj += __shfl_xor_sync(0xffffffffu, sj, o);
    }
    if (lane == 0) {
        g_e1i[hh * Lq + l] = __expf(si);
        g_e2i[hh * Lq + l] = __expf(0.2f * si);
        g_e1j[hh * Lq + l] = __expf(sj);
        g_e2j[hh * Lq + l] = __expf(0.2f * sj);
    }
}

// ---------------- mask kernel: transposed bitmask [word][row] ----------------
__global__ void __launch_bounds__(256) mask_kernel(const int* __restrict__ A) {
    int lane = threadIdx.x & 31, wid = threadIdx.x >> 5;
    int row = blockIdx.x * 8 + wid;
    const int* Arow = A + (size_t)row * Lq;
    for (int w = 0; w < Lq / 32; w++) {
        uint32_t b = __ballot_sync(0xffffffffu, Arow[w * 32 + lane] > 0);
        if (lane == 0) g_maskT[(size_t)w * Lq + row] = b;
    }
}

// ---------------- mma.sync attention: 128 rows x 1 head x half-K per CTA -----
// smem (66 KB -> 2 CTAs/SM):
//   b_s    : 2 x [64][36] f32    18432 B
//   e1j/e2j: [2048] f32 each     16384 B
//   mask_s : [64][128] u32       32768 B
#define BPAD   36
#define BBUF   (64 * BPAD)
#define SM_B    0
#define SM_E1J  (2 * BBUF * 4)             // 18432
#define SM_E2J  (SM_E1J + JHALF * 4)       // 26624
#define SM_MASK (SM_E2J + JHALF * 4)       // 34816
#define SM_TOT  (SM_MASK + JC * 128 * 4)   // 67584

__global__ void __launch_bounds__(256, 2) gat_attn_mma() {
    extern __shared__ char smem[];
    uint32_t smb = s2u(smem);
    float*    b_s    = (float*)(smem + SM_B);
    float*    e1j_s  = (float*)(smem + SM_E1J);
    float*    e2j_s  = (float*)(smem + SM_E2J);
    uint32_t* mask_s = (uint32_t*)(smem + SM_MASK);

    int tid = threadIdx.x, lane = tid & 31, wid = tid >> 5;
    int tile = blockIdx.x & 31;
    int h    = (blockIdx.x >> 5) & 3;
    int jh   = blockIdx.x >> 7;
    int i0   = tile * 128;
    int jb   = jh * JHALF;

    int q4 = lane & 3;
    int rg = lane >> 2;
    int r1 = wid * 16 + rg;
    int r2 = r1 + 8;

    float E1a = __ldg(&g_e1i[h * Lq + i0 + r1]);
    float E2a = __ldg(&g_e2i[h * Lq + i0 + r1]);
    float E1b = __ldg(&g_e1i[h * Lq + i0 + r2]);
    float E2b = __ldg(&g_e2i[h * Lq + i0 + r2]);

#define PREF_B(c, nb) do {                                                     \
        _Pragma("unroll")                                                      \
        for (int q = 0; q < 2; q++) {                                          \
            int idx = tid + q * 256;                                           \
            int n = idx >> 3, k4 = idx & 7;                                    \
            cpa16(smb + SM_B + (nb) * BBUF * 4 + n * BPAD * 4 + k4 * 16,       \
                  &g_WhT[(size_t)(h * HD + n) * Lq + jb + (c) * CJ + k4 * 4]); \
        }                                                                      \
        CPA_COMMIT();                                                          \
    } while (0)

    // ---- prologue: B chunk 0 + half-mask + half e tables ----
    PREF_B(0, 0);
#pragma unroll
    for (int q = 0; q < 8; q++) {          // 64 words x 128 rows = 2048 x 16B
        int idx = tid + q * 256;
        int w = idx >> 5, r4 = idx & 31;
        cpa16(smb + SM_MASK + idx * 16,
              &g_maskT[(size_t)(jh * JC + w) * Lq + i0 + r4 * 4]);
    }
#pragma unroll
    for (int q = 0; q < 2; q++) {
        int idx = tid + q * 256;
        cpa16(smb + SM_E1J + idx * 16, &g_e1j[h * Lq + jb + idx * 4]);
        cpa16(smb + SM_E2J + idx * 16, &g_e2j[h * Lq + jb + idx * 4]);
    }
    CPA_COMMIT();
    CPA_WAIT0();
    __syncthreads();

    float c_acc[8][4];
#pragma unroll
    for (int t = 0; t < 8; t++)
#pragma unroll
        for (int p = 0; p < 4; p++) c_acc[t][p] = 0.f;
    float dsum1 = 0.f, dsum2 = 0.f;

    for (int c = 0; c < JC; c++) {
        int cur = c & 1;
        if (c + 1 < JC) PREF_B(c + 1, cur ^ 1);

        uint32_t mw1 = mask_s[c * 128 + r1] >> q4;
        uint32_t mw2 = mask_s[c * 128 + r2] >> q4;
        const float* bb = b_s + cur * BBUF + rg * BPAD;

#pragma unroll
        for (int ks = 0; ks < 4; ks++) {
            int j = c * CJ + ks * 8 + q4;
            float e1a = e1j_s[j],     e2a = e2j_s[j];
            float e1b = e1j_s[j + 4], e2b = e2j_s[j + 4];
            float m0 = fmaxf(E1a * e1a, E2a * e2a);
            float m1 = fmaxf(E1b * e1a, E2b * e2a);
            float m2 = fmaxf(E1a * e1b, E2a * e2b);
            float m3 = fmaxf(E1b * e1b, E2b * e2b);
            m0 = (mw1 & (1u << (ks * 8)))     ? m0 : 0.f;
            m1 = (mw2 & (1u << (ks * 8)))     ? m1 : 0.f;
            m2 = (mw1 & (1u << (ks * 8 + 4))) ? m2 : 0.f;
            m3 = (mw2 & (1u << (ks * 8 + 4))) ? m3 : 0.f;
            dsum1 += m0 + m2;
            dsum2 += m1 + m3;
            // raw fp32 bits as tf32 operands (HW truncates low mantissa bits)
            uint32_t a0 = __float_as_uint(m0), a1 = __float_as_uint(m1);
            uint32_t a2 = __float_as_uint(m2), a3 = __float_as_uint(m3);
#pragma unroll
            for (int t = 0; t < 8; t++) {
                uint32_t b0 = *(const uint32_t*)&bb[t * 8 * BPAD + ks * 8 + q4];
                uint32_t b1 = *(const uint32_t*)&bb[t * 8 * BPAD + ks * 8 + q4 + 4];
                mma_tf32(c_acc[t], a0, a1, a2, a3, b0, b1);
            }
        }

        if (c + 1 < JC) CPA_WAIT0();
        __syncthreads();
    }

    // denominator: reduce across the 4 lanes sharing a row, write partial
#pragma unroll
    for (int o = 1; o <= 2; o <<= 1) {
        dsum1 += __shfl_xor_sync(0xffffffffu, dsum1, o);
        dsum2 += __shfl_xor_sync(0xffffffffu, dsum2, o);
    }
    if (q4 == 0) {
        g_den[(size_t)jh * NH * Lq + h * Lq + i0 + r1] = dsum1;
        g_den[(size_t)jh * NH * Lq + h * Lq + i0 + r2] = dsum2;
    }

    // partial (unnormalized) writeback
    int col0 = h * HD + q4 * 2;
    float* d1 = g_patt + (size_t)jh * Lq * DOUTC + (size_t)(i0 + r1) * DOUTC + col0;
    float* d2 = g_patt + (size_t)jh * Lq * DOUTC + (size_t)(i0 + r2) * DOUTC + col0;
#pragma unroll
    for (int t = 0; t < 8; t++) {
        *(float2*)(d1 + t * 8) = make_float2(c_acc[t][0], c_acc[t][1]);
        *(float2*)(d2 + t * 8) = make_float2(c_acc[t][2], c_acc[t][3]);
    }
}

// ---------------- combine: g_att = (P0 + P1) / (d0 + d1) ---------------------
__global__ void __launch_bounds__(256) combine_kernel() {
    int idx = blockIdx.x * 256 + threadIdx.x;     // float4 units
    int i  = idx >> 6;
    int c4 = idx & 63;
    int h  = c4 >> 4;
    float d = g_den[h * Lq + i] + g_den[NH * Lq + h * Lq + i];
    float inv = (d > 0.f) ? 1.f / d : 0.f;
    float4 p0 = *(const float4*)&g_patt[(size_t)idx * 4];
    float4 p1 = *(const float4*)&g_patt[(size_t)Lq * DOUTC + (size_t)idx * 4];
    float4 o = make_float4((p0.x + p1.x) * inv, (p0.y + p1.y) * inv,
                           (p0.z + p1.z) * inv, (p0.w + p1.w) * inv);
    *(float4*)&g_att[(size_t)idx * 4] = o;
}

// ---------------- launch ------------------------------------------------------
extern "C" void kernel_launch(void* const* d_in, const int* in_sizes, int n_in,
                              void* d_out, int out_size) {
    const float* h     = (const float*)d_in[0];
    const int*   A     = (const int*)d_in[1];
    const float* W     = (const float*)d_in[2];
    const float* attn  = (const float*)d_in[3];
    const float* out_w = (const float*)d_in[4];
    const float* out_b = (const float*)d_in[5];
    float*       out   = (float*)d_out;

    gemm64_nt<DIN, 0><<<dim3(DOUTC / 64, Lq / 64), 256>>>(h, W, nullptr, nullptr);
    mask_kernel<<<Lq / 8, 256>>>(A);
    s_kernel<<<(Lq * NH) / 8, 256>>>(attn);
    cudaFuncSetAttribute(gat_attn_mma,
                         cudaFuncAttributeMaxDynamicSharedMemorySize, SM_TOT);
    gat_attn_mma<<<(Lq / 128) * NH * 2, 256, SM_TOT>>>();
    combine_kernel<<<(Lq * DOUTC / 4) / 256, 256>>>();
    gemm64_nt<DOUTC, 1><<<dim3(DOUTC / 64, Lq / 64), 256>>>(nullptr, out_w, out, out_b);
}

// round 11
// speedup vs baseline: 5.7572x; 1.0873x over previous
#include <cuda_runtime.h>
#include <cstdint>

#define Lq    4096
#define DIN   512
#define DOUTC 256
#define NH    4
#define HD    64
#define CJ    32
#define JC    64
#define JHALF 2048

typedef unsigned long long ull;

// ---------------- scratch (device globals; no allocs allowed) ----------------
__device__ float    g_Wh[Lq * DOUTC];
__device__ float    g_WhT[DOUTC * Lq];
__device__ float    g_patt[2 * Lq * DOUTC];
__device__ float    g_den[2 * NH * Lq];
__device__ float    g_dinv[NH * Lq];
__device__ float    g_e1i[NH * Lq];
__device__ float    g_e2i[NH * Lq];
__device__ float    g_e1j[NH * Lq];
__device__ float    g_e2j[NH * Lq];
__device__ uint32_t g_maskT[(Lq / 32) * Lq];

__device__ __forceinline__ uint32_t tf32r(float x) {
    uint32_t u;
    asm("cvt.rna.tf32.f32 %0, %1;" : "=r"(u) : "f"(x));
    return u;
}
__device__ __forceinline__ uint32_t s2u(const void* p) {
    uint32_t a;
    asm("{ .reg .u64 t; cvta.to.shared.u64 t, %1; cvt.u32.u64 %0, t; }"
        : "=r"(a) : "l"(p));
    return a;
}
__device__ __forceinline__ void cpa16(uint32_t dst, const void* src) {
    asm volatile("cp.async.cg.shared.global [%0], [%1], 16;"
                 :: "r"(dst), "l"(src));
}
#define CPA_COMMIT() asm volatile("cp.async.commit_group;")
#define CPA_WAIT0()  asm volatile("cp.async.wait_group 0;")

__device__ __forceinline__ ull pack2(float x, float y) {
    ull r;
    asm("mov.b64 %0, {%1, %2};" : "=l"(r) : "f"(x), "f"(y));
    return r;
}
__device__ __forceinline__ void fma2(ull& d, ull a, ull b) {
    asm("fma.rn.f32x2 %0, %1, %2, %0;" : "+l"(d) : "l"(a), "l"(b));
}
__device__ __forceinline__ float2 unpack2(ull v) {
    float2 f;
    asm("mov.b64 {%0, %1}, %2;" : "=f"(f.x), "=f"(f.y) : "l"(v));
    return f;
}
__device__ __forceinline__ void mma_tf32(float* c, uint32_t a0, uint32_t a1,
                                         uint32_t a2, uint32_t a3,
                                         uint32_t b0, uint32_t b1) {
    asm volatile(
        "mma.sync.aligned.m16n8k8.row.col.f32.tf32.tf32.f32 "
        "{%0,%1,%2,%3}, {%4,%5,%6,%7}, {%8,%9}, {%0,%1,%2,%3};"
        : "+f"(c[0]), "+f"(c[1]), "+f"(c[2]), "+f"(c[3])
        : "r"(a0), "r"(a1), "r"(a2), "r"(a3), "r"(b0), "r"(b1));
}

// ---------------- pipelined f32x2 GEMM: C = A @ B^T (+bias) ------------------
// MODE 0: A = h,                          C = g_Wh (+ g_WhT tf32), K = DIN
// MODE 1: A = (g_patt0+g_patt1)*dinv,     C = out + bias,          K = DOUTC
template <int K, int MODE>
__global__ void __launch_bounds__(256) gemm64_nt(const float* __restrict__ Aext,
                                                 const float* __restrict__ Bm,
                                                 float* __restrict__ Cext,
                                                 const float* __restrict__ bias) {
    __shared__ float As[16][68];
    __shared__ float Bs[16][68];

    int tid = threadIdx.x;
    int m0 = blockIdx.y * 64, n0 = blockIdx.x * 64;
    int tx = tid & 15, ty = tid >> 4;
    int r  = tid >> 2;
    int kk = (tid & 3) * 4;

    // --- prefetch chunk 0 into regs ---
    float4 av, bv;
    {
        if (MODE == 0) {
            av = *(const float4*)&Aext[(size_t)(m0 + r) * K + kk];
        } else {
            float4 p0 = *(const float4*)&g_patt[(size_t)(m0 + r) * K + kk];
            float4 p1 = *(const float4*)&g_patt[(size_t)Lq * DOUTC +
                                                (size_t)(m0 + r) * K + kk];
            float inv = __ldg(&g_dinv[(kk >> 6) * Lq + m0 + r]);
            av = make_float4((p0.x + p1.x) * inv, (p0.y + p1.y) * inv,
                             (p0.z + p1.z) * inv, (p0.w + p1.w) * inv);
        }
        bv = *(const float4*)&Bm[(size_t)(n0 + r) * K + kk];
    }

    ull acc2[2][4];
#pragma unroll
    for (int p = 0; p < 2; p++)
#pragma unroll
        for (int j = 0; j < 4; j++) acc2[p][j] = 0ull;

    const int NCK = K / 16;
    for (int c = 0; c < NCK; c++) {
        // store prefetched chunk (prev compute finished at loop-end barrier)
        As[kk + 0][r] = av.x; As[kk + 1][r] = av.y;
        As[kk + 2][r] = av.z; As[kk + 3][r] = av.w;
        Bs[kk + 0][r] = bv.x; Bs[kk + 1][r] = bv.y;
        Bs[kk + 2][r] = bv.z; Bs[kk + 3][r] = bv.w;
        __syncthreads();

        // prefetch chunk c+1
        if (c + 1 < NCK) {
            int k0 = (c + 1) * 16;
            if (MODE == 0) {
                av = *(const float4*)&Aext[(size_t)(m0 + r) * K + k0 + kk];
            } else {
                float4 p0 = *(const float4*)&g_patt[(size_t)(m0 + r) * K + k0 + kk];
                float4 p1 = *(const float4*)&g_patt[(size_t)Lq * DOUTC +
                                                    (size_t)(m0 + r) * K + k0 + kk];
                float inv = __ldg(&g_dinv[((k0 + kk) >> 6) * Lq + m0 + r]);
                av = make_float4((p0.x + p1.x) * inv, (p0.y + p1.y) * inv,
                                 (p0.z + p1.z) * inv, (p0.w + p1.w) * inv);
            }
            bv = *(const float4*)&Bm[(size_t)(n0 + r) * K + k0 + kk];
        }

        // compute with f32x2 packed row-pairs
#pragma unroll
        for (int k = 0; k < 16; k++) {
            ulonglong2 aa = *(const ulonglong2*)&As[k][ty * 4];
            float4 b = *(const float4*)&Bs[k][tx * 4];
            ull bx = pack2(b.x, b.x), by = pack2(b.y, b.y);
            ull bz = pack2(b.z, b.z), bw = pack2(b.w, b.w);
            fma2(acc2[0][0], aa.x, bx); fma2(acc2[0][1], aa.x, by);
            fma2(acc2[0][2], aa.x, bz); fma2(acc2[0][3], aa.x, bw);
            fma2(acc2[1][0], aa.y, bx); fma2(acc2[1][1], aa.y, by);
            fma2(acc2[1][2], aa.y, bz); fma2(acc2[1][3], aa.y, bw);
        }
        __syncthreads();
    }

    // unpack accumulators
    float acc[4][4];
#pragma unroll
    for (int p = 0; p < 2; p++)
#pragma unroll
        for (int j = 0; j < 4; j++) {
            float2 v = unpack2(acc2[p][j]);
            acc[2 * p][j] = v.x;
            acc[2 * p + 1][j] = v.y;
        }

    float4 bvb = make_float4(0.f, 0.f, 0.f, 0.f);
    if (MODE == 1) bvb = *(const float4*)&bias[n0 + tx * 4];
    float* Cm = (MODE == 0) ? g_Wh : Cext;
#pragma unroll
    for (int i = 0; i < 4; i++) {
        float4 o = make_float4(acc[i][0] + bvb.x, acc[i][1] + bvb.y,
                               acc[i][2] + bvb.z, acc[i][3] + bvb.w);
        *(float4*)&Cm[(size_t)(m0 + ty * 4 + i) * DOUTC + n0 + tx * 4] = o;
    }
    if (MODE == 0) {
#pragma unroll
        for (int j = 0; j < 4; j++) {
            uint4 v;
            v.x = tf32r(acc[0][j]); v.y = tf32r(acc[1][j]);
            v.z = tf32r(acc[2][j]); v.w = tf32r(acc[3][j]);
            *(uint4*)&g_WhT[(size_t)(n0 + tx * 4 + j) * Lq + m0 + ty * 4] = v;
        }
    }
}

// ---------------- s kernel: E1/E2 factor tables ------------------------------
__global__ void __launch_bounds__(256) s_kernel(const float* __restrict__ attn) {
    int gw = blockIdx.x * 8 + (threadIdx.x >> 5);
    int lane = threadIdx.x & 31;
    int l = gw >> 2, hh = gw & 3;
    const float* whp = &g_Wh[(size_t)l * DOUTC + hh * HD];
    float v0 = whp[lane], v1 = whp[lane + 32];
    const float* ap = &attn[hh * 2 * HD];
    float si = v0 * ap[lane]      + v1 * ap[lane + 32];
    float sj = v0 * ap[64 + lane] + v1 * ap[96 + lane];
#pragma unroll
    for (int o = 16; o; o >>= 1) {
        si += __shfl_xor_sync(0xffffffffu, si, o);
        sj += __shfl_xor_sync(0xffffffffu, sj, o);
    }
    if (lane == 0) {
        g_e1i[hh * Lq + l] = __expf(si);
        g_e2i[hh * Lq + l] = __expf(0.2f * si);
        g_e1j[hh * Lq + l] = __expf(sj);
        g_e2j[hh * Lq + l] = __expf(0.2f * sj);
    }
}

// ---------------- mask kernel ------------------------------------------------
__global__ void __launch_bounds__(256) mask_kernel(const int* __restrict__ A) {
    int lane = threadIdx.x & 31, wid = threadIdx.x >> 5;
    int row = blockIdx.x * 8 + wid;
    const int* Arow = A + (size_t)row * Lq;
    for (int w = 0; w < Lq / 32; w++) {
        uint32_t b = __ballot_sync(0xffffffffu, Arow[w * 32 + lane] > 0);
        if (lane == 0) g_maskT[(size_t)w * Lq + row] = b;
    }
}

// ---------------- dinv: 1/(d0+d1) --------------------------------------------
__global__ void __launch_bounds__(256) dinv_kernel() {
    int idx = blockIdx.x * 256 + threadIdx.x;
    float d = g_den[idx] + g_den[NH * Lq + idx];
    g_dinv[idx] = (d > 0.f) ? 1.f / d : 0.f;
}

// ---------------- mma.sync attention (unchanged from R10) --------------------
#define BPAD   36
#define BBUF   (64 * BPAD)
#define SM_B    0
#define SM_E1J  (2 * BBUF * 4)
#define SM_E2J  (SM_E1J + JHALF * 4)
#define SM_MASK (SM_E2J + JHALF * 4)
#define SM_TOT  (SM_MASK + JC * 128 * 4)

__global__ void __launch_bounds__(256, 2) gat_attn_mma() {
    extern __shared__ char smem[];
    uint32_t smb = s2u(smem);
    float*    b_s    = (float*)(smem + SM_B);
    float*    e1j_s  = (float*)(smem + SM_E1J);
    float*    e2j_s  = (float*)(smem + SM_E2J);
    uint32_t* mask_s = (uint32_t*)(smem + SM_MASK);

    int tid = threadIdx.x, lane = tid & 31, wid = tid >> 5;
    int tile = blockIdx.x & 31;
    int h    = (blockIdx.x >> 5) & 3;
    int jh   = blockIdx.x >> 7;
    int i0   = tile * 128;
    int jb   = jh * JHALF;

    int q4 = lane & 3;
    int rg = lane >> 2;
    int r1 = wid * 16 + rg;
    int r2 = r1 + 8;

    float E1a = __ldg(&g_e1i[h * Lq + i0 + r1]);
    float E2a = __ldg(&g_e2i[h * Lq + i0 + r1]);
    float E1b = __ldg(&g_e1i[h * Lq + i0 + r2]);
    float E2b = __ldg(&g_e2i[h * Lq + i0 + r2]);

#define PREF_B(c, nb) do {                                                     \
        _Pragma("unroll")                                                      \
        for (int q = 0; q < 2; q++) {                                          \
            int idx = tid + q * 256;                                           \
            int n = idx >> 3, k4 = idx & 7;                                    \
            cpa16(smb + SM_B + (nb) * BBUF * 4 + n * BPAD * 4 + k4 * 16,       \
                  &g_WhT[(size_t)(h * HD + n) * Lq + jb + (c) * CJ + k4 * 4]); \
        }                                                                      \
        CPA_COMMIT();                                                          \
    } while (0)

    PREF_B(0, 0);
#pragma unroll
    for (int q = 0; q < 8; q++) {
        int idx = tid + q * 256;
        int w = idx >> 5, r4 = idx & 31;
        cpa16(smb + SM_MASK + idx * 16,
              &g_maskT[(size_t)(jh * JC + w) * Lq + i0 + r4 * 4]);
    }
#pragma unroll
    for (int q = 0; q < 2; q++) {
        int idx = tid + q * 256;
        cpa16(smb + SM_E1J + idx * 16, &g_e1j[h * Lq + jb + idx * 4]);
        cpa16(smb + SM_E2J + idx * 16, &g_e2j[h * Lq + jb + idx * 4]);
    }
    CPA_COMMIT();
    CPA_WAIT0();
    __syncthreads();

    float c_acc[8][4];
#pragma unroll
    for (int t = 0; t < 8; t++)
#pragma unroll
        for (int p = 0; p < 4; p++) c_acc[t][p] = 0.f;
    float dsum1 = 0.f, dsum2 = 0.f;

    for (int c = 0; c < JC; c++) {
        int cur = c & 1;
        if (c + 1 < JC) PREF_B(c + 1, cur ^ 1);

        uint32_t mw1 = mask_s[c * 128 + r1] >> q4;
        uint32_t mw2 = mask_s[c * 128 + r2] >> q4;
        const float* bb = b_s + cur * BBUF + rg * BPAD;

#pragma unroll
        for (int ks = 0; ks < 4; ks++) {
            int j = c * CJ + ks * 8 + q4;
            float e1a = e1j_s[j],     e2a = e2j_s[j];
            float e1b = e1j_s[j + 4], e2b = e2j_s[j + 4];
            float m0 = fmaxf(E1a * e1a, E2a * e2a);
            float m1 = fmaxf(E1b * e1a, E2b * e2a);
            float m2 = fmaxf(E1a * e1b, E2a * e2b);
            float m3 = fmaxf(E1b * e1b, E2b * e2b);
            m0 = (mw1 & (1u << (ks * 8)))     ? m0 : 0.f;
            m1 = (mw2 & (1u << (ks * 8)))     ? m1 : 0.f;
            m2 = (mw1 & (1u << (ks * 8 + 4))) ? m2 : 0.f;
            m3 = (mw2 & (1u << (ks * 8 + 4))) ? m3 : 0.f;
            dsum1 += m0 + m2;
            dsum2 += m1 + m3;
            uint32_t a0 = __float_as_uint(m0), a1 = __float_as_uint(m1);
            uint32_t a2 = __float_as_uint(m2), a3 = __float_as_uint(m3);
#pragma unroll
            for (int t = 0; t < 8; t++) {
                uint32_t b0 = *(const uint32_t*)&bb[t * 8 * BPAD + ks * 8 + q4];
                uint32_t b1 = *(const uint32_t*)&bb[t * 8 * BPAD + ks * 8 + q4 + 4];
                mma_tf32(c_acc[t], a0, a1, a2, a3, b0, b1);
            }
        }

        if (c + 1 < JC) CPA_WAIT0();
        __syncthreads();
    }

#pragma unroll
    for (int o = 1; o <= 2; o <<= 1) {
        dsum1 += __shfl_xor_sync(0xffffffffu, dsum1, o);
        dsum2 += __shfl_xor_sync(0xffffffffu, dsum2, o);
    }
    if (q4 == 0) {
        g_den[(size_t)jh * NH * Lq + h * Lq + i0 + r1] = dsum1;
        g_den[(size_t)jh * NH * Lq + h * Lq + i0 + r2] = dsum2;
    }

    int col0 = h * HD + q4 * 2;
    float* d1 = g_patt + (size_t)jh * Lq * DOUTC + (size_t)(i0 + r1) * DOUTC + col0;
    float* d2 = g_patt + (size_t)jh * Lq * DOUTC + (size_t)(i0 + r2) * DOUTC + col0;
#pragma unroll
    for (int t = 0; t < 8; t++) {
        *(float2*)(d1 + t * 8) = make_float2(c_acc[t][0], c_acc[t][1]);
        *(float2*)(d2 + t * 8) = make_float2(c_acc[t][2], c_acc[t][3]);
    }
}

// ---------------- launch ------------------------------------------------------
extern "C" void kernel_launch(void* const* d_in, const int* in_sizes, int n_in,
                              void* d_out, int out_size) {
    const float* h     = (const float*)d_in[0];
    const int*   A     = (const int*)d_in[1];
    const float* W     = (const float*)d_in[2];
    const float* attn  = (const float*)d_in[3];
    const float* out_w = (const float*)d_in[4];
    const float* out_b = (const float*)d_in[5];
    float*       out   = (float*)d_out;

    gemm64_nt<DIN, 0><<<dim3(DOUTC / 64, Lq / 64), 256>>>(h, W, nullptr, nullptr);
    mask_kernel<<<Lq / 8, 256>>>(A);
    s_kernel<<<(Lq * NH) / 8, 256>>>(attn);
    cudaFuncSetAttribute(gat_attn_mma,
                         cudaFuncAttributeMaxDynamicSharedMemorySize, SM_TOT);
    gat_attn_mma<<<(Lq / 128) * NH * 2, 256, SM_TOT>>>();
    dinv_kernel<<<(NH * Lq) / 256, 256>>>();
    gemm64_nt<DOUTC, 1><<<dim3(DOUTC / 64, Lq / 64), 256>>>(nullptr, out_w, out, out_b);
}

// round 12
// speedup vs baseline: 5.8238x; 1.0116x over previous
#include <cuda_runtime.h>
#include <cstdint>

#define Lq    4096
#define DIN   512
#define DOUTC 256
#define NH    4
#define HD    64
#define CJ    32
#define JC    64
#define JHALF 2048

typedef unsigned long long ull;

// ---------------- scratch (device globals; no allocs allowed) ----------------
__device__ float    g_Wh[Lq * DOUTC];
__device__ float    g_WhT[DOUTC * Lq];        // [c][l], k-paired within 8-blocks
__device__ float    g_patt[2 * Lq * DOUTC];
__device__ float    g_den[2 * NH * Lq];
__device__ float    g_dinv[NH * Lq];
__device__ float    g_e1i[NH * Lq];
__device__ float    g_e2i[NH * Lq];
__device__ float    g_ejp[NH * Lq * 2];       // paired (e1,e2,e1+4,e2+4) per (blk,q)
__device__ uint32_t g_maskT[(Lq / 32) * Lq];

__device__ __forceinline__ uint32_t tf32r(float x) {
    uint32_t u;
    asm("cvt.rna.tf32.f32 %0, %1;" : "=r"(u) : "f"(x));
    return u;
}
__device__ __forceinline__ uint32_t s2u(const void* p) {
    uint32_t a;
    asm("{ .reg .u64 t; cvta.to.shared.u64 t, %1; cvt.u32.u64 %0, t; }"
        : "=r"(a) : "l"(p));
    return a;
}
__device__ __forceinline__ void cpa16(uint32_t dst, const void* src) {
    asm volatile("cp.async.cg.shared.global [%0], [%1], 16;"
                 :: "r"(dst), "l"(src));
}
#define CPA_COMMIT() asm volatile("cp.async.commit_group;")
#define CPA_WAIT0()  asm volatile("cp.async.wait_group 0;")

__device__ __forceinline__ ull pack2(float x, float y) {
    ull r;
    asm("mov.b64 %0, {%1, %2};" : "=l"(r) : "f"(x), "f"(y));
    return r;
}
__device__ __forceinline__ void fma2(ull& d, ull a, ull b) {
    asm("fma.rn.f32x2 %0, %1, %2, %0;" : "+l"(d) : "l"(a), "l"(b));
}
__device__ __forceinline__ float2 unpack2(ull v) {
    float2 f;
    asm("mov.b64 {%0, %1}, %2;" : "=f"(f.x), "=f"(f.y) : "l"(v));
    return f;
}
__device__ __forceinline__ void mma_tf32(float* c, uint32_t a0, uint32_t a1,
                                         uint32_t a2, uint32_t a3,
                                         uint32_t b0, uint32_t b1) {
    asm volatile(
        "mma.sync.aligned.m16n8k8.row.col.f32.tf32.tf32.f32 "
        "{%0,%1,%2,%3}, {%4,%5,%6,%7}, {%8,%9}, {%0,%1,%2,%3};"
        : "+f"(c[0]), "+f"(c[1]), "+f"(c[2]), "+f"(c[3])
        : "r"(a0), "r"(a1), "r"(a2), "r"(a3), "r"(b0), "r"(b1));
}

// ---------------- pipelined f32x2 GEMM: C = A @ B^T (+bias) ------------------
template <int K, int MODE>
__global__ void __launch_bounds__(256) gemm64_nt(const float* __restrict__ Aext,
                                                 const float* __restrict__ Bm,
                                                 float* __restrict__ Cext,
                                                 const float* __restrict__ bias) {
    __shared__ float As[16][68];
    __shared__ float Bs[16][68];

    int tid = threadIdx.x;
    int m0 = blockIdx.y * 64, n0 = blockIdx.x * 64;
    int tx = tid & 15, ty = tid >> 4;
    int r  = tid >> 2;
    int kk = (tid & 3) * 4;

    float4 av, bv;
    {
        if (MODE == 0) {
            av = *(const float4*)&Aext[(size_t)(m0 + r) * K + kk];
        } else {
            float4 p0 = *(const float4*)&g_patt[(size_t)(m0 + r) * K + kk];
            float4 p1 = *(const float4*)&g_patt[(size_t)Lq * DOUTC +
                                                (size_t)(m0 + r) * K + kk];
            float inv = __ldg(&g_dinv[(kk >> 6) * Lq + m0 + r]);
            av = make_float4((p0.x + p1.x) * inv, (p0.y + p1.y) * inv,
                             (p0.z + p1.z) * inv, (p0.w + p1.w) * inv);
        }
        bv = *(const float4*)&Bm[(size_t)(n0 + r) * K + kk];
    }

    ull acc2[2][4];
#pragma unroll
    for (int p = 0; p < 2; p++)
#pragma unroll
        for (int j = 0; j < 4; j++) acc2[p][j] = 0ull;

    const int NCK = K / 16;
    for (int c = 0; c < NCK; c++) {
        As[kk + 0][r] = av.x; As[kk + 1][r] = av.y;
        As[kk + 2][r] = av.z; As[kk + 3][r] = av.w;
        Bs[kk + 0][r] = bv.x; Bs[kk + 1][r] = bv.y;
        Bs[kk + 2][r] = bv.z; Bs[kk + 3][r] = bv.w;
        __syncthreads();

        if (c + 1 < NCK) {
            int k0 = (c + 1) * 16;
            if (MODE == 0) {
                av = *(const float4*)&Aext[(size_t)(m0 + r) * K + k0 + kk];
            } else {
                float4 p0 = *(const float4*)&g_patt[(size_t)(m0 + r) * K + k0 + kk];
                float4 p1 = *(const float4*)&g_patt[(size_t)Lq * DOUTC +
                                                    (size_t)(m0 + r) * K + k0 + kk];
                float inv = __ldg(&g_dinv[((k0 + kk) >> 6) * Lq + m0 + r]);
                av = make_float4((p0.x + p1.x) * inv, (p0.y + p1.y) * inv,
                                 (p0.z + p1.z) * inv, (p0.w + p1.w) * inv);
            }
            bv = *(const float4*)&Bm[(size_t)(n0 + r) * K + k0 + kk];
        }

#pragma unroll
        for (int k = 0; k < 16; k++) {
            ulonglong2 aa = *(const ulonglong2*)&As[k][ty * 4];
            float4 b = *(const float4*)&Bs[k][tx * 4];
            ull bx = pack2(b.x, b.x), by = pack2(b.y, b.y);
            ull bz = pack2(b.z, b.z), bw = pack2(b.w, b.w);
            fma2(acc2[0][0], aa.x, bx); fma2(acc2[0][1], aa.x, by);
            fma2(acc2[0][2], aa.x, bz); fma2(acc2[0][3], aa.x, bw);
            fma2(acc2[1][0], aa.y, bx); fma2(acc2[1][1], aa.y, by);
            fma2(acc2[1][2], aa.y, bz); fma2(acc2[1][3], aa.y, bw);
        }
        __syncthreads();
    }

    float acc[4][4];
#pragma unroll
    for (int p = 0; p < 2; p++)
#pragma unroll
        for (int j = 0; j < 4; j++) {
            float2 v = unpack2(acc2[p][j]);
            acc[2 * p][j] = v.x;
            acc[2 * p + 1][j] = v.y;
        }

    float4 bvb = make_float4(0.f, 0.f, 0.f, 0.f);
    if (MODE == 1) bvb = *(const float4*)&bias[n0 + tx * 4];
    float* Cm = (MODE == 0) ? g_Wh : Cext;
#pragma unroll
    for (int i = 0; i < 4; i++) {
        float4 o = make_float4(acc[i][0] + bvb.x, acc[i][1] + bvb.y,
                               acc[i][2] + bvb.z, acc[i][3] + bvb.w);
        *(float4*)&Cm[(size_t)(m0 + ty * 4 + i) * DOUTC + n0 + tx * 4] = o;
    }
    if (MODE == 0) {
        // k-paired tf32 store: within each 8-block of l, order (0,4,1,5,2,6,3,7)
        // position p = 2*(l&3) + ((l>>2)&1)
#pragma unroll
        for (int j = 0; j < 4; j++) {
#pragma unroll
            for (int i = 0; i < 4; i++) {
                int l = m0 + ty * 4 + i;
                int p = 2 * (l & 3) + ((l >> 2) & 1);
                g_WhT[(size_t)(n0 + tx * 4 + j) * Lq + (l & ~7) + p] =
                    __uint_as_float(tf32r(acc[i][j]));
            }
        }
    }
}

// ---------------- s kernel: row factors + paired j tables --------------------
// exp(lrelu(si+sj)) == max(exp(si)exp(sj), exp(.2si)exp(.2sj))
__global__ void __launch_bounds__(256) s_kernel(const float* __restrict__ attn) {
    int gw = blockIdx.x * 8 + (threadIdx.x >> 5);
    int lane = threadIdx.x & 31;
    int l = gw >> 2, hh = gw & 3;
    const float* whp = &g_Wh[(size_t)l * DOUTC + hh * HD];
    float v0 = whp[lane], v1 = whp[lane + 32];
    const float* ap = &attn[hh * 2 * HD];
    float si = v0 * ap[lane]      + v1 * ap[lane + 32];
    float sj = v0 * ap[64 + lane] + v1 * ap[96 + lane];
#pragma unroll
    for (int o = 16; o; o >>= 1) {
        si += __shfl_xor_sync(0xffffffffu, si, o);
        sj += __shfl_xor_sync(0xffffffffu, sj, o);
    }
    if (lane == 0) {
        g_e1i[hh * Lq + l] = __expf(si);
        g_e2i[hh * Lq + l] = __expf(0.2f * si);
        // paired layout: float4 (e1[j],e2[j],e1[j+4],e2[j+4]) per (block, q)
        int block = l >> 3, t8 = l & 7;
        int q = t8 & 3, hi = t8 >> 2;
        float* dst = &g_ejp[(size_t)(((hh * (Lq / 8) + block) * 4 + q) * 4) + hi * 2];
        dst[0] = __expf(sj);
        dst[1] = __expf(0.2f * sj);
    }
}

// ---------------- mask kernel ------------------------------------------------
__global__ void __launch_bounds__(256) mask_kernel(const int* __restrict__ A) {
    int lane = threadIdx.x & 31, wid = threadIdx.x >> 5;
    int row = blockIdx.x * 8 + wid;
    const int* Arow = A + (size_t)row * Lq;
    for (int w = 0; w < Lq / 32; w++) {
        uint32_t b = __ballot_sync(0xffffffffu, Arow[w * 32 + lane] > 0);
        if (lane == 0) g_maskT[(size_t)w * Lq + row] = b;
    }
}

// ---------------- dinv: 1/(d0+d1) --------------------------------------------
__global__ void __launch_bounds__(256) dinv_kernel() {
    int idx = blockIdx.x * 256 + threadIdx.x;
    float d = g_den[idx] + g_den[NH * Lq + idx];
    g_dinv[idx] = (d > 0.f) ? 1.f / d : 0.f;
}

// ---------------- mma.sync attention: 128 rows x 1 head x half-K per CTA -----
// smem (68 KB, 2 CTAs/SM):
//   b_s   : 2 x [64][40] f32   20480 B (k-paired, BPAD=40 conflict-free LDS.64)
//   ejp_s : [JHALF/8][4] f4    16384 B
//   mask_s: [64][128] u32      32768 B
#define BPAD   40
#define BBUF   (64 * BPAD)
#define SM_B    0
#define SM_EJP  (2 * BBUF * 4)             // 20480
#define SM_MASK (SM_EJP + JHALF * 2 * 4)   // 36864
#define SM_TOT  (SM_MASK + JC * 128 * 4)   // 69632

__global__ void __launch_bounds__(256, 2) gat_attn_mma() {
    extern __shared__ char smem[];
    uint32_t smb = s2u(smem);
    float*        b_s    = (float*)(smem + SM_B);
    const float4* ejp_s  = (const float4*)(smem + SM_EJP);
    uint32_t*     mask_s = (uint32_t*)(smem + SM_MASK);

    int tid = threadIdx.x, lane = tid & 31, wid = tid >> 5;
    int tile = blockIdx.x & 31;
    int h    = (blockIdx.x >> 5) & 3;
    int jh   = blockIdx.x >> 7;
    int i0   = tile * 128;
    int jb   = jh * JHALF;

    int q4 = lane & 3;
    int rg = lane >> 2;
    int r1 = wid * 16 + rg;
    int r2 = r1 + 8;

    float E1a = __ldg(&g_e1i[h * Lq + i0 + r1]);
    float E2a = __ldg(&g_e2i[h * Lq + i0 + r1]);
    float E1b = __ldg(&g_e1i[h * Lq + i0 + r2]);
    float E2b = __ldg(&g_e2i[h * Lq + i0 + r2]);

#define PREF_B(c, nb) do {                                                     \
        _Pragma("unroll")                                                      \
        for (int q = 0; q < 2; q++) {                                          \
            int idx = tid + q * 256;                                           \
            int n = idx >> 3, k4 = idx & 7;                                    \
            cpa16(smb + SM_B + (nb) * BBUF * 4 + n * (BPAD * 4) + k4 * 16,     \
                  &g_WhT[(size_t)(h * HD + n) * Lq + jb + (c) * CJ + k4 * 4]); \
        }                                                                      \
        CPA_COMMIT();                                                          \
    } while (0)

    PREF_B(0, 0);
#pragma unroll
    for (int q = 0; q < 8; q++) {
        int idx = tid + q * 256;
        int w = idx >> 5, r4 = idx & 31;
        cpa16(smb + SM_MASK + idx * 16,
              &g_maskT[(size_t)(jh * JC + w) * Lq + i0 + r4 * 4]);
    }
#pragma unroll
    for (int q = 0; q < 4; q++) {        // ejp half: 4096 floats = 1024 x 16B
        int idx = tid + q * 256;
        cpa16(smb + SM_EJP + idx * 16,
              &g_ejp[(size_t)(h * (Lq / 8) + jb / 8) * 16 + idx * 4]);
    }
    CPA_COMMIT();
    CPA_WAIT0();
    __syncthreads();

    float c_acc[8][4];
#pragma unroll
    for (int t = 0; t < 8; t++)
#pragma unroll
        for (int p = 0; p < 4; p++) c_acc[t][p] = 0.f;
    float dsum1 = 0.f, dsum2 = 0.f;

    for (int c = 0; c < JC; c++) {
        int cur = c & 1;
        if (c + 1 < JC) PREF_B(c + 1, cur ^ 1);

        uint32_t mw1 = mask_s[c * 128 + r1] >> q4;
        uint32_t mw2 = mask_s[c * 128 + r2] >> q4;
        const float* bb = b_s + cur * BBUF + rg * BPAD;

#pragma unroll
        for (int ks = 0; ks < 4; ks++) {
            float4 ee = ejp_s[(c * 4 + ks) * 4 + q4];   // e1a,e2a,e1b,e2b
            float m0 = fmaxf(E1a * ee.x, E2a * ee.y);
            float m1 = fmaxf(E1b * ee.x, E2b * ee.y);
            float m2 = fmaxf(E1a * ee.z, E2a * ee.w);
            float m3 = fmaxf(E1b * ee.z, E2b * ee.w);
            m0 = (mw1 & (1u << (ks * 8)))     ? m0 : 0.f;
            m1 = (mw2 & (1u << (ks * 8)))     ? m1 : 0.f;
            m2 = (mw1 & (1u << (ks * 8 + 4))) ? m2 : 0.f;
            m3 = (mw2 & (1u << (ks * 8 + 4))) ? m3 : 0.f;
            dsum1 += m0 + m2;
            dsum2 += m1 + m3;
            uint32_t a0 = __float_as_uint(m0), a1 = __float_as_uint(m1);
            uint32_t a2 = __float_as_uint(m2), a3 = __float_as_uint(m3);
#pragma unroll
            for (int t = 0; t < 8; t++) {
                uint2 b01 = *(const uint2*)&bb[t * 8 * BPAD + ks * 8 + q4 * 2];
                mma_tf32(c_acc[t], a0, a1, a2, a3, b01.x, b01.y);
            }
        }

        if (c + 1 < JC) CPA_WAIT0();
        __syncthreads();
    }

#pragma unroll
    for (int o = 1; o <= 2; o <<= 1) {
        dsum1 += __shfl_xor_sync(0xffffffffu, dsum1, o);
        dsum2 += __shfl_xor_sync(0xffffffffu, dsum2, o);
    }
    if (q4 == 0) {
        g_den[(size_t)jh * NH * Lq + h * Lq + i0 + r1] = dsum1;
        g_den[(size_t)jh * NH * Lq + h * Lq + i0 + r2] = dsum2;
    }

    int col0 = h * HD + q4 * 2;
    float* d1 = g_patt + (size_t)jh * Lq * DOUTC + (size_t)(i0 + r1) * DOUTC + col0;
    float* d2 = g_patt + (size_t)jh * Lq * DOUTC + (size_t)(i0 + r2) * DOUTC + col0;
#pragma unroll
    for (int t = 0; t < 8; t++) {
        *(float2*)(d1 + t * 8) = make_float2(c_acc[t][0], c_acc[t][1]);
        *(float2*)(d2 + t * 8) = make_float2(c_acc[t][2], c_acc[t][3]);
    }
}

// ---------------- launch ------------------------------------------------------
extern "C" void kernel_launch(void* const* d_in, const int* in_sizes, int n_in,
                              void* d_out, int out_size) {
    const float* h     = (const float*)d_in[0];
    const int*   A     = (const int*)d_in[1];
    const float* W     = (const float*)d_in[2];
    const float* attn  = (const float*)d_in[3];
    const float* out_w = (const float*)d_in[4];
    const float* out_b = (const float*)d_in[5];
    float*       out   = (float*)d_out;

    gemm64_nt<DIN, 0><<<dim3(DOUTC / 64, Lq / 64), 256>>>(h, W, nullptr, nullptr);
    mask_kernel<<<Lq / 8, 256>>>(A);
    s_kernel<<<(Lq * NH) / 8, 256>>>(attn);
    cudaFuncSetAttribute(gat_attn_mma,
                         cudaFuncAttributeMaxDynamicSharedMemorySize, SM_TOT);
    gat_attn_mma<<<(Lq / 128) * NH * 2, 256, SM_TOT>>>();
    dinv_kernel<<<(NH * Lq) / 256, 256>>>();
    gemm64_nt<DOUTC, 1><<<dim3(DOUTC / 64, Lq / 64), 256>>>(nullptr, out_w, out, out_b);
}

// round 13
// speedup vs baseline: 6.0710x; 1.0424x over previous
#include <cuda_runtime.h>
#include <cstdint>

#define Lq    4096
#define DIN   512
#define DOUTC 256
#define NH    4
#define HD    64
#define CJ    32
#define JC    64
#define JHALF 2048

typedef unsigned long long ull;

// ---------------- scratch (device globals; no allocs allowed) ----------------
__device__ float    g_Wh[Lq * DOUTC];
__device__ float    g_WhT[DOUTC * Lq];        // [c][l], k-paired within 8-blocks
__device__ float    g_patt[2 * Lq * DOUTC];
__device__ float    g_den[2 * NH * Lq];
__device__ float    g_dinv[NH * Lq];
__device__ float    g_e1i[NH * Lq];
__device__ float    g_e2i[NH * Lq];
__device__ float    g_ejp[NH * Lq * 2];       // paired (e1,e2,e1+4,e2+4) per (blk,q)
__device__ uint32_t g_maskT[(Lq / 32) * Lq];

__device__ __forceinline__ uint32_t tf32r(float x) {
    uint32_t u;
    asm("cvt.rna.tf32.f32 %0, %1;" : "=r"(u) : "f"(x));
    return u;
}
__device__ __forceinline__ uint32_t s2u(const void* p) {
    uint32_t a;
    asm("{ .reg .u64 t; cvta.to.shared.u64 t, %1; cvt.u32.u64 %0, t; }"
        : "=r"(a) : "l"(p));
    return a;
}
__device__ __forceinline__ void cpa16(uint32_t dst, const void* src) {
    asm volatile("cp.async.cg.shared.global [%0], [%1], 16;"
                 :: "r"(dst), "l"(src));
}
#define CPA_COMMIT() asm volatile("cp.async.commit_group;")
#define CPA_WAIT0()  asm volatile("cp.async.wait_group 0;")

__device__ __forceinline__ ull pack2(float x, float y) {
    ull r;
    asm("mov.b64 %0, {%1, %2};" : "=l"(r) : "f"(x), "f"(y));
    return r;
}
__device__ __forceinline__ void fma2(ull& d, ull a, ull b) {
    asm("fma.rn.f32x2 %0, %1, %2, %0;" : "+l"(d) : "l"(a), "l"(b));
}
__device__ __forceinline__ float2 unpack2(ull v) {
    float2 f;
    asm("mov.b64 {%0, %1}, %2;" : "=f"(f.x), "=f"(f.y) : "l"(v));
    return f;
}
__device__ __forceinline__ void mma_tf32(float* c, uint32_t a0, uint32_t a1,
                                         uint32_t a2, uint32_t a3,
                                         uint32_t b0, uint32_t b1) {
    asm volatile(
        "mma.sync.aligned.m16n8k8.row.col.f32.tf32.tf32.f32 "
        "{%0,%1,%2,%3}, {%4,%5,%6,%7}, {%8,%9}, {%0,%1,%2,%3};"
        : "+f"(c[0]), "+f"(c[1]), "+f"(c[2]), "+f"(c[3])
        : "r"(a0), "r"(a1), "r"(a2), "r"(a3), "r"(b0), "r"(b1));
}

// ---------------- pipelined f32x2 GEMM: C = A @ B^T (+bias) ------------------
template <int K, int MODE>
__global__ void __launch_bounds__(256) gemm64_nt(const float* __restrict__ Aext,
                                                 const float* __restrict__ Bm,
                                                 float* __restrict__ Cext,
                                                 const float* __restrict__ bias) {
    __shared__ float As[16][68];
    __shared__ float Bs[16][68];

    int tid = threadIdx.x;
    int m0 = blockIdx.y * 64, n0 = blockIdx.x * 64;
    int tx = tid & 15, ty = tid >> 4;
    int r  = tid >> 2;
    int kk = (tid & 3) * 4;

    float4 av, bv;
    {
        if (MODE == 0) {
            av = *(const float4*)&Aext[(size_t)(m0 + r) * K + kk];
        } else {
            float4 p0 = *(const float4*)&g_patt[(size_t)(m0 + r) * K + kk];
            float4 p1 = *(const float4*)&g_patt[(size_t)Lq * DOUTC +
                                                (size_t)(m0 + r) * K + kk];
            float inv = __ldg(&g_dinv[(kk >> 6) * Lq + m0 + r]);
            av = make_float4((p0.x + p1.x) * inv, (p0.y + p1.y) * inv,
                             (p0.z + p1.z) * inv, (p0.w + p1.w) * inv);
        }
        bv = *(const float4*)&Bm[(size_t)(n0 + r) * K + kk];
    }

    ull acc2[2][4];
#pragma unroll
    for (int p = 0; p < 2; p++)
#pragma unroll
        for (int j = 0; j < 4; j++) acc2[p][j] = 0ull;

    const int NCK = K / 16;
    for (int c = 0; c < NCK; c++) {
        As[kk + 0][r] = av.x; As[kk + 1][r] = av.y;
        As[kk + 2][r] = av.z; As[kk + 3][r] = av.w;
        Bs[kk + 0][r] = bv.x; Bs[kk + 1][r] = bv.y;
        Bs[kk + 2][r] = bv.z; Bs[kk + 3][r] = bv.w;
        __syncthreads();

        if (c + 1 < NCK) {
            int k0 = (c + 1) * 16;
            if (MODE == 0) {
                av = *(const float4*)&Aext[(size_t)(m0 + r) * K + k0 + kk];
            } else {
                float4 p0 = *(const float4*)&g_patt[(size_t)(m0 + r) * K + k0 + kk];
                float4 p1 = *(const float4*)&g_patt[(size_t)Lq * DOUTC +
                                                    (size_t)(m0 + r) * K + k0 + kk];
                float inv = __ldg(&g_dinv[((k0 + kk) >> 6) * Lq + m0 + r]);
                av = make_float4((p0.x + p1.x) * inv, (p0.y + p1.y) * inv,
                                 (p0.z + p1.z) * inv, (p0.w + p1.w) * inv);
            }
            bv = *(const float4*)&Bm[(size_t)(n0 + r) * K + k0 + kk];
        }

#pragma unroll
        for (int k = 0; k < 16; k++) {
            ulonglong2 aa = *(const ulonglong2*)&As[k][ty * 4];
            float4 b = *(const float4*)&Bs[k][tx * 4];
            ull bx = pack2(b.x, b.x), by = pack2(b.y, b.y);
            ull bz = pack2(b.z, b.z), bw = pack2(b.w, b.w);
            fma2(acc2[0][0], aa.x, bx); fma2(acc2[0][1], aa.x, by);
            fma2(acc2[0][2], aa.x, bz); fma2(acc2[0][3], aa.x, bw);
            fma2(acc2[1][0], aa.y, bx); fma2(acc2[1][1], aa.y, by);
            fma2(acc2[1][2], aa.y, bz); fma2(acc2[1][3], aa.y, bw);
        }
        __syncthreads();
    }

    float acc[4][4];
#pragma unroll
    for (int p = 0; p < 2; p++)
#pragma unroll
        for (int j = 0; j < 4; j++) {
            float2 v = unpack2(acc2[p][j]);
            acc[2 * p][j] = v.x;
            acc[2 * p + 1][j] = v.y;
        }

    float4 bvb = make_float4(0.f, 0.f, 0.f, 0.f);
    if (MODE == 1) bvb = *(const float4*)&bias[n0 + tx * 4];
    float* Cm = (MODE == 0) ? g_Wh : Cext;
#pragma unroll
    for (int i = 0; i < 4; i++) {
        float4 o = make_float4(acc[i][0] + bvb.x, acc[i][1] + bvb.y,
                               acc[i][2] + bvb.z, acc[i][3] + bvb.w);
        *(float4*)&Cm[(size_t)(m0 + ty * 4 + i) * DOUTC + n0 + tx * 4] = o;
    }
    if (MODE == 0) {
        // k-paired tf32 store: within each 8-block of l, order (0,4,1,5,2,6,3,7)
#pragma unroll
        for (int j = 0; j < 4; j++) {
#pragma unroll
            for (int i = 0; i < 4; i++) {
                int l = m0 + ty * 4 + i;
                int p = 2 * (l & 3) + ((l >> 2) & 1);
                g_WhT[(size_t)(n0 + tx * 4 + j) * Lq + (l & ~7) + p] =
                    __uint_as_float(tf32r(acc[i][j]));
            }
        }
    }
}

// ---------------- s kernel: row factors + paired j tables --------------------
__global__ void __launch_bounds__(256) s_kernel(const float* __restrict__ attn) {
    int gw = blockIdx.x * 8 + (threadIdx.x >> 5);
    int lane = threadIdx.x & 31;
    int l = gw >> 2, hh = gw & 3;
    const float* whp = &g_Wh[(size_t)l * DOUTC + hh * HD];
    float v0 = whp[lane], v1 = whp[lane + 32];
    const float* ap = &attn[hh * 2 * HD];
    float si = v0 * ap[lane]      + v1 * ap[lane + 32];
    float sj = v0 * ap[64 + lane] + v1 * ap[96 + lane];
#pragma unroll
    for (int o = 16; o; o >>= 1) {
        si += __shfl_xor_sync(0xffffffffu, si, o);
        sj += __shfl_xor_sync(0xffffffffu, sj, o);
    }
    if (lane == 0) {
        g_e1i[hh * Lq + l] = __expf(si);
        g_e2i[hh * Lq + l] = __expf(0.2f * si);
        int block = l >> 3, t8 = l & 7;
        int q = t8 & 3, hi = t8 >> 2;
        float* dst = &g_ejp[(size_t)(((hh * (Lq / 8) + block) * 4 + q) * 4) + hi * 2];
        dst[0] = __expf(sj);
        dst[1] = __expf(0.2f * sj);
    }
}

// ---------------- mask kernel ------------------------------------------------
__global__ void __launch_bounds__(256) mask_kernel(const int* __restrict__ A) {
    int lane = threadIdx.x & 31, wid = threadIdx.x >> 5;
    int row = blockIdx.x * 8 + wid;
    const int* Arow = A + (size_t)row * Lq;
    for (int w = 0; w < Lq / 32; w++) {
        uint32_t b = __ballot_sync(0xffffffffu, Arow[w * 32 + lane] > 0);
        if (lane == 0) g_maskT[(size_t)w * Lq + row] = b;
    }
}

// ---------------- dinv: 1/(d0+d1) --------------------------------------------
__global__ void __launch_bounds__(256) dinv_kernel() {
    int idx = blockIdx.x * 256 + threadIdx.x;
    float d = g_den[idx] + g_den[NH * Lq + idx];
    g_dinv[idx] = (d > 0.f) ? 1.f / d : 0.f;
}

// ---------------- mma.sync attention: 128 threads, warp = 32 rows ------------
// smem (68 KB):
//   b_s   : 2 x [64][40] f32   20480 B (k-paired, BPAD=40)
//   ejp_s : [JHALF/8][4] f4    16384 B
//   mask_s: [64][128] u32      32768 B
#define BPAD   40
#define BBUF   (64 * BPAD)
#define SM_B    0
#define SM_EJP  (2 * BBUF * 4)
#define SM_MASK (SM_EJP + JHALF * 2 * 4)
#define SM_TOT  (SM_MASK + JC * 128 * 4)

__global__ void __launch_bounds__(128, 3) gat_attn_mma() {
    extern __shared__ char smem[];
    uint32_t smb = s2u(smem);
    float*        b_s    = (float*)(smem + SM_B);
    const float4* ejp_s  = (const float4*)(smem + SM_EJP);
    uint32_t*     mask_s = (uint32_t*)(smem + SM_MASK);

    int tid = threadIdx.x, lane = tid & 31, wid = tid >> 5;
    int tile = blockIdx.x & 31;
    int h    = (blockIdx.x >> 5) & 3;
    int jh   = blockIdx.x >> 7;
    int i0   = tile * 128;
    int jb   = jh * JHALF;

    int q4 = lane & 3;
    int rg = lane >> 2;
    int rbase = wid * 32 + rg;       // warp owns rows rbase + {0,8,16,24}

    float E1[4], E2[4];
#pragma unroll
    for (int rr = 0; rr < 4; rr++) {
        E1[rr] = __ldg(&g_e1i[h * Lq + i0 + rbase + rr * 8]);
        E2[rr] = __ldg(&g_e2i[h * Lq + i0 + rbase + rr * 8]);
    }

#define PREF_B(c, nb) do {                                                     \
        _Pragma("unroll")                                                      \
        for (int q = 0; q < 4; q++) {                                          \
            int idx = tid + q * 128;                                           \
            int n = idx >> 3, k4 = idx & 7;                                    \
            cpa16(smb + SM_B + (nb) * BBUF * 4 + n * (BPAD * 4) + k4 * 16,     \
                  &g_WhT[(size_t)(h * HD + n) * Lq + jb + (c) * CJ + k4 * 4]); \
        }                                                                      \
        CPA_COMMIT();                                                          \
    } while (0)

    PREF_B(0, 0);
#pragma unroll
    for (int q = 0; q < 16; q++) {
        int idx = tid + q * 128;
        int w = idx >> 5, r4 = idx & 31;
        cpa16(smb + SM_MASK + idx * 16,
              &g_maskT[(size_t)(jh * JC + w) * Lq + i0 + r4 * 4]);
    }
#pragma unroll
    for (int q = 0; q < 8; q++) {
        int idx = tid + q * 128;
        cpa16(smb + SM_EJP + idx * 16,
              &g_ejp[(size_t)(h * (Lq / 8) + jb / 8) * 16 + idx * 4]);
    }
    CPA_COMMIT();
    CPA_WAIT0();
    __syncthreads();

    float c_acc[2][8][4];
#pragma unroll
    for (int tt = 0; tt < 2; tt++)
#pragma unroll
        for (int t = 0; t < 8; t++)
#pragma unroll
            for (int p = 0; p < 4; p++) c_acc[tt][t][p] = 0.f;
    float dsum[4] = {0.f, 0.f, 0.f, 0.f};

    for (int c = 0; c < JC; c++) {
        int cur = c & 1;
        if (c + 1 < JC) PREF_B(c + 1, cur ^ 1);

        uint32_t mw[4];
#pragma unroll
        for (int rr = 0; rr < 4; rr++)
            mw[rr] = mask_s[c * 128 + rbase + rr * 8] >> q4;
        const float* bb = b_s + cur * BBUF + rg * BPAD;

#pragma unroll
        for (int ks = 0; ks < 4; ks++) {
            float4 ee = ejp_s[(c * 4 + ks) * 4 + q4];   // e1a,e2a,e1b,e2b
            float ma[4], mb[4];
#pragma unroll
            for (int rr = 0; rr < 4; rr++) {
                float v1 = fmaxf(E1[rr] * ee.x, E2[rr] * ee.y);
                float v2 = fmaxf(E1[rr] * ee.z, E2[rr] * ee.w);
                ma[rr] = (mw[rr] & (1u << (ks * 8)))     ? v1 : 0.f;
                mb[rr] = (mw[rr] & (1u << (ks * 8 + 4))) ? v2 : 0.f;
                dsum[rr] += ma[rr] + mb[rr];
            }
            uint32_t a00 = __float_as_uint(ma[0]), a01 = __float_as_uint(ma[1]);
            uint32_t a02 = __float_as_uint(mb[0]), a03 = __float_as_uint(mb[1]);
            uint32_t a10 = __float_as_uint(ma[2]), a11 = __float_as_uint(ma[3]);
            uint32_t a12 = __float_as_uint(mb[2]), a13 = __float_as_uint(mb[3]);
#pragma unroll
            for (int t = 0; t < 8; t++) {
                uint2 b01 = *(const uint2*)&bb[t * 8 * BPAD + ks * 8 + q4 * 2];
                mma_tf32(c_acc[0][t], a00, a01, a02, a03, b01.x, b01.y);
                mma_tf32(c_acc[1][t], a10, a11, a12, a13, b01.x, b01.y);
            }
        }

        if (c + 1 < JC) CPA_WAIT0();
        __syncthreads();
    }

    // denominators: reduce over the 4 lanes sharing a row
#pragma unroll
    for (int rr = 0; rr < 4; rr++) {
#pragma unroll
        for (int o = 1; o <= 2; o <<= 1)
            dsum[rr] += __shfl_xor_sync(0xffffffffu, dsum[rr], o);
    }
    if (q4 == 0) {
#pragma unroll
        for (int rr = 0; rr < 4; rr++)
            g_den[(size_t)jh * NH * Lq + h * Lq + i0 + rbase + rr * 8] = dsum[rr];
    }

    // partial writeback
    int col0 = h * HD + q4 * 2;
#pragma unroll
    for (int tt = 0; tt < 2; tt++) {
        int row1 = i0 + rbase + tt * 16;
        int row2 = row1 + 8;
        float* d1 = g_patt + (size_t)jh * Lq * DOUTC + (size_t)row1 * DOUTC + col0;
        float* d2 = g_patt + (size_t)jh * Lq * DOUTC + (size_t)row2 * DOUTC + col0;
#pragma unroll
        for (int t = 0; t < 8; t++) {
            *(float2*)(d1 + t * 8) = make_float2(c_acc[tt][t][0], c_acc[tt][t][1]);
            *(float2*)(d2 + t * 8) = make_float2(c_acc[tt][t][2], c_acc[tt][t][3]);
        }
    }
}

// ---------------- launch ------------------------------------------------------
extern "C" void kernel_launch(void* const* d_in, const int* in_sizes, int n_in,
                              void* d_out, int out_size) {
    const float* h     = (const float*)d_in[0];
    const int*   A     = (const int*)d_in[1];
    const float* W     = (const float*)d_in[2];
    const float* attn  = (const float*)d_in[3];
    const float* out_w = (const float*)d_in[4];
    const float* out_b = (const float*)d_in[5];
    float*       out   = (float*)d_out;

    gemm64_nt<DIN, 0><<<dim3(DOUTC / 64, Lq / 64), 256>>>(h, W, nullptr, nullptr);
    mask_kernel<<<Lq / 8, 256>>>(A);
    s_kernel<<<(Lq * NH) / 8, 256>>>(attn);
    cudaFuncSetAttribute(gat_attn_mma,
                         cudaFuncAttributeMaxDynamicSharedMemorySize, SM_TOT);
    gat_attn_mma<<<(Lq / 128) * NH * 2, 128, SM_TOT>>>();
    dinv_kernel<<<(NH * Lq) / 256, 256>>>();
    gemm64_nt<DOUTC, 1><<<dim3(DOUTC / 64, Lq / 64), 256>>>(nullptr, out_w, out, out_b);
}